// round 3
// baseline (speedup 1.0000x reference)
#include <cuda_runtime.h>
#include <math.h>

#define SS 512
#define PP 64
#define TT 8
#define NN (SS*PP)            // 32768

#define ENC_ELEMS (NN*72)     // 2359296
#define SEQ_ELEMS (TT*NN*32)  // 8388608

__device__ float g_graph_in[SEQ_ELEMS];        // GAT output -> graph LSTM input
__device__ float g_x2[(size_t)SS*TT*64*64];    // GAT layer0 output (elu'd)
__device__ float g_traj_fb[SEQ_ELEMS];
__device__ float g_graph_fb[SEQ_ELEMS];

__device__ __forceinline__ float tanh_fast(float x){
    float y; asm("tanh.approx.f32 %0, %1;" : "=f"(y) : "f"(x)); return y;
}
__device__ __forceinline__ float sig_fast(float x){
    return 0.5f * tanh_fast(0.5f * x) + 0.5f;
}
__device__ __forceinline__ void fma4(float4& a, float s, const float4 w){
    a.x += s*w.x; a.y += s*w.y; a.z += s*w.z; a.w += s*w.w;
}

// ---------------------------------------------------------------------------
// LSTM traj: input dim 3, hidden 32, T=8. lane = hidden unit, 2 peds/thread.
// Weights packed float4 by gate: sWhh4[k*32+lane] = {Wi,Wf,Wg,Wo rows at lane}.
// ---------------------------------------------------------------------------
__global__ void __launch_bounds__(256, 4) lstm_traj_kernel(const float* __restrict__ x,
        const float* __restrict__ h0, const float* __restrict__ c0,
        const float* __restrict__ Wih, const float* __restrict__ Whh,
        const float* __restrict__ bih, const float* __restrict__ bhh,
        float* __restrict__ hs)
{
    __shared__ __align__(16) float4 sWhh4[1024];  // [k][lane] -> gates
    __shared__ __align__(16) float4 sWihP[96];    // [j][lane] -> gates (j=0..2)
    __shared__ __align__(16) float4 sb4[32];      // [lane] -> gates
    const int tid = threadIdx.x;

    for (int i = tid; i < 4096; i += 256) {
        int r = i >> 5, k = i & 31;
        ((float*)sWhh4)[(k*32 + (r & 31))*4 + (r >> 5)] = Whh[i];
    }
    for (int i = tid; i < 384; i += 256) {
        int r = i / 3, j = i - r*3;
        ((float*)sWihP)[(j*32 + (r & 31))*4 + (r >> 5)] = Wih[i];
    }
    if (tid < 32) {
        float4 b;
        b.x = bih[tid]      + bhh[tid];
        b.y = bih[32 + tid] + bhh[32 + tid];
        b.z = bih[64 + tid] + bhh[64 + tid];
        b.w = bih[96 + tid] + bhh[96 + tid];
        sb4[tid] = b;
    }
    __syncthreads();

    const int lane = tid & 31;
    const int n0 = blockIdx.x * 16 + (tid >> 5) * 2;

    float h[2], c[2];
    #pragma unroll
    for (int r = 0; r < 2; r++) { h[r] = h0[(n0+r)*32 + lane]; c[r] = c0[(n0+r)*32 + lane]; }

    #pragma unroll
    for (int t = 0; t < TT; t++) {
        float4 a[2];
        const float4 w0 = sWihP[lane], w1 = sWihP[32 + lane], w2 = sWihP[64 + lane];
        const float4 bb = sb4[lane];
        #pragma unroll
        for (int r = 0; r < 2; r++) {
            const float* xp = x + ((size_t)t*NN + n0 + r) * 3;
            float x0 = xp[0], x1 = xp[1], x2 = xp[2];
            a[r] = bb;
            fma4(a[r], x0, w0); fma4(a[r], x1, w1); fma4(a[r], x2, w2);
        }
        #pragma unroll
        for (int k = 0; k < 32; k++) {
            float4 w = sWhh4[k*32 + lane];
            float h0k = __shfl_sync(0xffffffffu, h[0], k);
            float h1k = __shfl_sync(0xffffffffu, h[1], k);
            fma4(a[0], h0k, w);
            fma4(a[1], h1k, w);
        }
        #pragma unroll
        for (int r = 0; r < 2; r++) {
            c[r] = sig_fast(a[r].y) * c[r] + sig_fast(a[r].x) * tanh_fast(a[r].z);
            h[r] = sig_fast(a[r].w) * tanh_fast(c[r]);
            hs[((size_t)t*NN + n0 + r)*32 + lane] = h[r];
        }
    }
}

// ---------------------------------------------------------------------------
// GAT layer 0: one block per (scene, timestep) graph.
// ---------------------------------------------------------------------------
__global__ void gat0_kernel(const float* __restrict__ traj,
        const float* __restrict__ w0, const float* __restrict__ as0,
        const float* __restrict__ ad0, const float* __restrict__ b0)
{
    __shared__ __align__(16) float pool[4096];  // [0:2048)=x, [2048:4096)=w; later attn[64][64]
    __shared__ __align__(16) float shp[4096];   // hp[p][h*16+o]
    __shared__ float sS[256], sD[256];
    __shared__ __align__(16) float smean[32], sinv[32];
    __shared__ float srinv[64];
    __shared__ float sas[64], sad[64];
    __shared__ __align__(16) float4 sb0v[4];

    float4* sx4 = (float4*)pool;            // 512 float4
    float4* sw4 = (float4*)(pool + 2048);   // 512 float4: w(h,f,o4) at h*128+f*4+o4
    const int tid = threadIdx.x;
    const int b = blockIdx.x, sIdx = b >> 3, tIdx = b & 7;

    {
        const float4* src = (const float4*)(traj + ((size_t)tIdx*NN + sIdx*64) * 32);
        for (int i = tid; i < 512; i += 256) sx4[i] = src[i];
        const float4* wsrc = (const float4*)w0;
        for (int i = tid; i < 512; i += 256) sw4[i] = wsrc[i];
        if (tid < 64) { sas[tid] = as0[tid]; sad[tid] = ad0[tid]; }
        if (tid < 4)  sb0v[tid] = ((const float4*)b0)[tid];
    }
    __syncthreads();

    // instance norm stats over p per feature
    if (tid < 32) {
        const float* xs = pool;
        float s = 0.f, s2 = 0.f;
        for (int p = 0; p < 64; p++) { float v = xs[p*32 + tid]; s += v; s2 += v*v; }
        float m = s * (1.0f/64.0f);
        float var = s2 * (1.0f/64.0f) - m*m;
        smean[tid] = m; sinv[tid] = rsqrtf(var + 1e-5f);
    }
    __syncthreads();
    for (int i = tid; i < 512; i += 256) {
        int f4 = i & 7;
        float4 m4 = ((float4*)smean)[f4], i4 = ((float4*)sinv)[f4];
        float4 v = sx4[i];
        v.x = (v.x - m4.x)*i4.x; v.y = (v.y - m4.y)*i4.y;
        v.z = (v.z - m4.z)*i4.z; v.w = (v.w - m4.w)*i4.w;
        sx4[i] = v;
    }
    __syncthreads();

    // hp[p][hh*16 + o4*4 + e] : 1024 items of 4 outputs
    for (int it = tid; it < 1024; it += 256) {
        int p = it >> 4, j = it & 15, hh = j >> 2, o4 = j & 3;
        float4 acc = {0.f,0.f,0.f,0.f};
        #pragma unroll
        for (int f4 = 0; f4 < 8; f4++) {
            float4 xv = sx4[p*8 + f4];
            fma4(acc, xv.x, sw4[hh*128 + (f4*4+0)*4 + o4]);
            fma4(acc, xv.y, sw4[hh*128 + (f4*4+1)*4 + o4]);
            fma4(acc, xv.z, sw4[hh*128 + (f4*4+2)*4 + o4]);
            fma4(acc, xv.w, sw4[hh*128 + (f4*4+3)*4 + o4]);
        }
        ((float4*)shp)[p*16 + hh*4 + o4] = acc;
    }
    __syncthreads();

    // s[h][p], d[h][p]
    {
        int hh = tid >> 6, p = tid & 63;
        const float4* hp4 = (const float4*)shp;
        float as = 0.f, ad = 0.f;
        #pragma unroll
        for (int o4 = 0; o4 < 4; o4++) {
            float4 v = hp4[p*16 + hh*4 + o4];
            int ob = hh*16 + o4*4;
            as += v.x*sas[ob] + v.y*sas[ob+1] + v.z*sas[ob+2] + v.w*sas[ob+3];
            ad += v.x*sad[ob] + v.y*sad[ob+1] + v.z*sad[ob+2] + v.w*sad[ob+3];
        }
        sS[tid] = as; sD[tid] = ad;
    }
    __syncthreads();

    float* sattn = pool;  // [64][64], overlays x+w (both dead)

    for (int hh = 0; hh < 4; hh++) {
        // softmax: 4 threads per row
        {
            int p = tid >> 2, q = tid & 3;
            float sp = sS[hh*64 + p];
            float l[16]; float mx = -1e30f;
            #pragma unroll
            for (int mm = 0; mm < 16; mm++) {
                float v = sp + sD[hh*64 + q*16 + mm];
                v = (v > 0.f) ? v : 0.2f*v;
                l[mm] = v; mx = fmaxf(mx, v);
            }
            mx = fmaxf(mx, __shfl_xor_sync(0xffffffffu, mx, 1));
            mx = fmaxf(mx, __shfl_xor_sync(0xffffffffu, mx, 2));
            float sum = 0.f;
            #pragma unroll
            for (int mm = 0; mm < 16; mm++) {
                float e = __expf(l[mm] - mx);
                sattn[p*64 + q*16 + mm] = e; sum += e;
            }
            sum += __shfl_xor_sync(0xffffffffu, sum, 1);
            sum += __shfl_xor_sync(0xffffffffu, sum, 2);
            if (q == 0) srinv[p] = 1.0f / sum;
        }
        __syncthreads();
        // apply: thread = (p, o4)
        {
            int p = tid >> 2, o4 = tid & 3;
            const float* ap = &sattn[p*64];
            const float4* hp4 = (const float4*)shp;
            float4 acc = {0.f,0.f,0.f,0.f};
            #pragma unroll
            for (int m = 0; m < 64; m++) fma4(acc, ap[m], hp4[m*16 + hh*4 + o4]);
            float ri = srinv[p];
            float4 bb = sb0v[o4];
            float4 res;
            res.x = acc.x*ri + bb.x; res.y = acc.y*ri + bb.y;
            res.z = acc.z*ri + bb.z; res.w = acc.w*ri + bb.w;
            res.x = (res.x > 0.f) ? res.x : (__expf(res.x) - 1.f);
            res.y = (res.y > 0.f) ? res.y : (__expf(res.y) - 1.f);
            res.z = (res.z > 0.f) ? res.z : (__expf(res.z) - 1.f);
            res.w = (res.w > 0.f) ? res.w : (__expf(res.w) - 1.f);
            ((float4*)g_x2)[((size_t)b*64 + p)*16 + hh*4 + o4] = res;
        }
        __syncthreads();
    }
}

// ---------------------------------------------------------------------------
// GAT layer 1: x2[64,64] -> norm -> hp[64,32] -> attention -> g_graph_in
// ---------------------------------------------------------------------------
__global__ void gat1_kernel(const float* __restrict__ w1, const float* __restrict__ as1,
        const float* __restrict__ ad1, const float* __restrict__ b1)
{
    __shared__ __align__(16) float pool[4096];  // sx / sattn
    __shared__ __align__(16) float sw[2048];    // w(f,o4) at f*8+o4 (float4)
    __shared__ __align__(16) float shp[2048];
    __shared__ float sS[64], sD[64];
    __shared__ __align__(16) float smean[64], sinv[64];
    __shared__ float srinv[64], sas[32], sad[32];
    __shared__ __align__(16) float4 sb1v[8];

    float4* sx4 = (float4*)pool;          // 1024 float4
    float4* sw4 = (float4*)sw;            // 512 float4
    const int tid = threadIdx.x;
    const int b = blockIdx.x, sIdx = b >> 3, tIdx = b & 7;

    {
        const float4* src = (const float4*)(g_x2 + (size_t)b*4096);
        for (int i = tid; i < 1024; i += 256) sx4[i] = src[i];
        const float4* wsrc = (const float4*)w1;
        for (int i = tid; i < 512; i += 256) sw4[i] = wsrc[i];
        if (tid < 32) { sas[tid] = as1[tid]; sad[tid] = ad1[tid]; }
        if (tid < 8)  sb1v[tid] = ((const float4*)b1)[tid];
    }
    __syncthreads();

    if (tid < 64) {
        float s = 0.f, s2 = 0.f;
        for (int p = 0; p < 64; p++) { float v = pool[p*64 + tid]; s += v; s2 += v*v; }
        float m = s * (1.0f/64.0f);
        float var = s2 * (1.0f/64.0f) - m*m;
        smean[tid] = m; sinv[tid] = rsqrtf(var + 1e-5f);
    }
    __syncthreads();
    for (int i = tid; i < 1024; i += 256) {
        int f4 = i & 15;
        float4 m4 = ((float4*)smean)[f4], i4 = ((float4*)sinv)[f4];
        float4 v = sx4[i];
        v.x = (v.x - m4.x)*i4.x; v.y = (v.y - m4.y)*i4.y;
        v.z = (v.z - m4.z)*i4.z; v.w = (v.w - m4.w)*i4.w;
        sx4[i] = v;
    }
    __syncthreads();

    // hp: 512 items (p, o4), 2 per thread
    for (int it = tid; it < 512; it += 256) {
        int p = it >> 3, o4 = it & 7;
        float4 acc = {0.f,0.f,0.f,0.f};
        #pragma unroll
        for (int f4 = 0; f4 < 16; f4++) {
            float4 xv = sx4[p*16 + f4];
            fma4(acc, xv.x, sw4[(f4*4+0)*8 + o4]);
            fma4(acc, xv.y, sw4[(f4*4+1)*8 + o4]);
            fma4(acc, xv.z, sw4[(f4*4+2)*8 + o4]);
            fma4(acc, xv.w, sw4[(f4*4+3)*8 + o4]);
        }
        ((float4*)shp)[p*8 + o4] = acc;
    }
    __syncthreads();

    if (tid < 64) {
        int p = tid;
        const float4* hp4 = (const float4*)shp;
        float as = 0.f, ad = 0.f;
        #pragma unroll
        for (int o4 = 0; o4 < 8; o4++) {
            float4 v = hp4[p*8 + o4];
            as += v.x*sas[o4*4] + v.y*sas[o4*4+1] + v.z*sas[o4*4+2] + v.w*sas[o4*4+3];
            ad += v.x*sad[o4*4] + v.y*sad[o4*4+1] + v.z*sad[o4*4+2] + v.w*sad[o4*4+3];
        }
        sS[p] = as; sD[p] = ad;
    }
    __syncthreads();

    float* sattn = pool;  // overlays x (dead)
    {
        int p = tid >> 2, q = tid & 3;
        float sp = sS[p];
        float l[16]; float mx = -1e30f;
        #pragma unroll
        for (int mm = 0; mm < 16; mm++) {
            float v = sp + sD[q*16 + mm];
            v = (v > 0.f) ? v : 0.2f*v;
            l[mm] = v; mx = fmaxf(mx, v);
        }
        mx = fmaxf(mx, __shfl_xor_sync(0xffffffffu, mx, 1));
        mx = fmaxf(mx, __shfl_xor_sync(0xffffffffu, mx, 2));
        float sum = 0.f;
        #pragma unroll
        for (int mm = 0; mm < 16; mm++) {
            float e = __expf(l[mm] - mx);
            sattn[p*64 + q*16 + mm] = e; sum += e;
        }
        sum += __shfl_xor_sync(0xffffffffu, sum, 1);
        sum += __shfl_xor_sync(0xffffffffu, sum, 2);
        if (q == 0) srinv[p] = 1.0f / sum;
    }
    __syncthreads();

    for (int it = tid; it < 512; it += 256) {
        int p = it >> 3, o4 = it & 7;
        const float* ap = &sattn[p*64];
        const float4* hp4 = (const float4*)shp;
        float4 acc = {0.f,0.f,0.f,0.f};
        #pragma unroll
        for (int m = 0; m < 64; m++) fma4(acc, ap[m], hp4[m*8 + o4]);
        float ri = srinv[p];
        float4 bb = sb1v[o4];
        float4 res;
        res.x = acc.x*ri + bb.x; res.y = acc.y*ri + bb.y;
        res.z = acc.z*ri + bb.z; res.w = acc.w*ri + bb.w;
        ((float4*)g_graph_in)[((size_t)tIdx*NN + sIdx*64 + p)*8 + o4] = res;
    }
}

// ---------------------------------------------------------------------------
// LSTM graph: input dim 32, hidden 32, T=8. lane = hidden, 2 peds/thread.
// ---------------------------------------------------------------------------
__global__ void __launch_bounds__(256, 4) lstm_graph_kernel(
        const float* __restrict__ h0, const float* __restrict__ c0,
        const float* __restrict__ Wih, const float* __restrict__ Whh,
        const float* __restrict__ bih, const float* __restrict__ bhh,
        float* __restrict__ hs)
{
    __shared__ __align__(16) float4 sWih4[1024];
    __shared__ __align__(16) float4 sWhh4[1024];
    __shared__ __align__(16) float4 sb4[32];
    const int tid = threadIdx.x;

    for (int i = tid; i < 4096; i += 256) {
        int r = i >> 5, k = i & 31;
        int idx = (k*32 + (r & 31))*4 + (r >> 5);
        ((float*)sWih4)[idx] = Wih[i];
        ((float*)sWhh4)[idx] = Whh[i];
    }
    if (tid < 32) {
        float4 b;
        b.x = bih[tid]      + bhh[tid];
        b.y = bih[32 + tid] + bhh[32 + tid];
        b.z = bih[64 + tid] + bhh[64 + tid];
        b.w = bih[96 + tid] + bhh[96 + tid];
        sb4[tid] = b;
    }
    __syncthreads();

    const int lane = tid & 31;
    const int n0 = blockIdx.x * 16 + (tid >> 5) * 2;

    float h[2], c[2];
    #pragma unroll
    for (int r = 0; r < 2; r++) { h[r] = h0[(n0+r)*32 + lane]; c[r] = c0[(n0+r)*32 + lane]; }

    #pragma unroll
    for (int t = 0; t < TT; t++) {
        float4 a[2];
        float xv[2];
        const float4 bb = sb4[lane];
        #pragma unroll
        for (int r = 0; r < 2; r++) {
            xv[r] = g_graph_in[((size_t)t*NN + n0 + r)*32 + lane];
            a[r] = bb;
        }
        #pragma unroll
        for (int k = 0; k < 32; k++) {
            float4 wi = sWih4[k*32 + lane];
            float4 wh = sWhh4[k*32 + lane];
            float x0k = __shfl_sync(0xffffffffu, xv[0], k);
            float h0k = __shfl_sync(0xffffffffu, h[0],  k);
            float x1k = __shfl_sync(0xffffffffu, xv[1], k);
            float h1k = __shfl_sync(0xffffffffu, h[1],  k);
            fma4(a[0], x0k, wi);
            fma4(a[0], h0k, wh);
            fma4(a[1], x1k, wi);
            fma4(a[1], h1k, wh);
        }
        #pragma unroll
        for (int r = 0; r < 2; r++) {
            c[r] = sig_fast(a[r].y) * c[r] + sig_fast(a[r].x) * tanh_fast(a[r].z);
            h[r] = sig_fast(a[r].w) * tanh_fast(c[r]);
            hs[((size_t)t*NN + n0 + r)*32 + lane] = h[r];
        }
    }
}

// ---------------------------------------------------------------------------
// Concat (float4): encoded[n] = [traj_hs[7,n] | graph_hs[7,n] | z[n/64]]
// ---------------------------------------------------------------------------
__global__ void concat_kernel(const float* __restrict__ z,
        const float* __restrict__ traj, const float* __restrict__ graph,
        float* __restrict__ out)
{
    int idx = blockIdx.x * blockDim.x + threadIdx.x;
    if (idx >= NN*18) return;
    int n = idx / 18, j = idx - n*18;
    float4 v;
    if (j < 8)       v = ((const float4*)traj)[((size_t)7*NN + n)*8 + j];
    else if (j < 16) v = ((const float4*)graph)[((size_t)7*NN + n)*8 + (j - 8)];
    else             v = ((const float4*)z)[(n >> 6)*2 + (j - 16)];
    ((float4*)out)[idx] = v;
}

extern "C" void kernel_launch(void* const* d_in, const int* in_sizes, int n_in,
                              void* d_out, int out_size) {
    const float* obs  = (const float*)d_in[0];
    const float* h0t  = (const float*)d_in[1];
    const float* c0t  = (const float*)d_in[2];
    const float* h0g  = (const float*)d_in[3];
    const float* c0g  = (const float*)d_in[4];
    const float* z    = (const float*)d_in[5];
    const float* WihT = (const float*)d_in[6];
    const float* WhhT = (const float*)d_in[7];
    const float* bihT = (const float*)d_in[8];
    const float* bhhT = (const float*)d_in[9];
    const float* WihG = (const float*)d_in[10];
    const float* WhhG = (const float*)d_in[11];
    const float* bihG = (const float*)d_in[12];
    const float* bhhG = (const float*)d_in[13];
    const float* w0   = (const float*)d_in[14];
    const float* as0  = (const float*)d_in[15];
    const float* ad0  = (const float*)d_in[16];
    const float* b0   = (const float*)d_in[17];
    const float* w1   = (const float*)d_in[18];
    const float* as1  = (const float*)d_in[19];
    const float* ad1  = (const float*)d_in[20];
    const float* b1   = (const float*)d_in[21];
    float* out = (float*)d_out;

    float* traj_hs;
    float* graph_hs;
    if (out_size >= ENC_ELEMS + 2*SEQ_ELEMS) {
        graph_hs = out + ENC_ELEMS;
        traj_hs  = out + ENC_ELEMS + SEQ_ELEMS;
    } else {
        void* pt = nullptr; void* pg = nullptr;
        cudaGetSymbolAddress(&pt, g_traj_fb);
        cudaGetSymbolAddress(&pg, g_graph_fb);
        traj_hs  = (float*)pt;
        graph_hs = (float*)pg;
    }

    lstm_traj_kernel<<<NN/16, 256>>>(obs, h0t, c0t, WihT, WhhT, bihT, bhhT, traj_hs);
    gat0_kernel<<<SS*TT, 256>>>(traj_hs, w0, as0, ad0, b0);
    gat1_kernel<<<SS*TT, 256>>>(w1, as1, ad1, b1);
    lstm_graph_kernel<<<NN/16, 256>>>(h0g, c0g, WihG, WhhG, bihG, bhhG, graph_hs);
    concat_kernel<<<(NN*18 + 255)/256, 256>>>(z, traj_hs, graph_hs, out);
}

// round 4
// speedup vs baseline: 1.6289x; 1.6289x over previous
#include <cuda_runtime.h>
#include <math.h>

#define SS 512
#define PP 64
#define TT 8
#define NN (SS*PP)            // 32768

#define ENC_ELEMS (NN*72)     // 2359296
#define SEQ_ELEMS (TT*NN*32)  // 8388608

__device__ float g_graph_in[SEQ_ELEMS];        // GAT output -> graph LSTM input
__device__ float g_x2[(size_t)SS*TT*64*64];    // GAT layer0 output (elu'd)
__device__ float g_gates[(size_t)TT*NN*128];   // precomputed x@WihG^T + bias (128MB)
__device__ float g_traj_fb[SEQ_ELEMS];
__device__ float g_graph_fb[SEQ_ELEMS];

__device__ __forceinline__ float tanh_fast(float x){
    float y; asm("tanh.approx.f32 %0, %1;" : "=f"(y) : "f"(x)); return y;
}
__device__ __forceinline__ float sig_fast(float x){
    return 0.5f * tanh_fast(0.5f * x) + 0.5f;
}
__device__ __forceinline__ void fma4(float4& a, float s, const float4 w){
    a.x += s*w.x; a.y += s*w.y; a.z += s*w.z; a.w += s*w.w;
}

// ---------------------------------------------------------------------------
// LSTM traj (R1 structure): warp = 1 ped, lane = hidden unit.
// ---------------------------------------------------------------------------
__global__ void lstm_traj_kernel(const float* __restrict__ x,
        const float* __restrict__ h0, const float* __restrict__ c0,
        const float* __restrict__ Wih, const float* __restrict__ Whh,
        const float* __restrict__ bih, const float* __restrict__ bhh,
        float* __restrict__ hs)
{
    __shared__ float sWih[384];     // [128][3]
    __shared__ float sWhhT[4096];   // [32][128] (k-major)
    __shared__ float sb[128];
    const int tid = threadIdx.x;
    for (int i = tid; i < 384; i += 256) sWih[i] = Wih[i];
    for (int i = tid; i < 4096; i += 256) { int row = i >> 5, k = i & 31; sWhhT[k*128 + row] = Whh[i]; }
    if (tid < 128) sb[tid] = bih[tid] + bhh[tid];
    __syncthreads();

    const int lane = tid & 31;
    const int n = blockIdx.x * 8 + (tid >> 5);
    float h = h0[n*32 + lane];
    float c = c0[n*32 + lane];

    #pragma unroll
    for (int t = 0; t < TT; t++) {
        const float* xp = x + ((size_t)t*NN + n) * 3;
        float x0 = xp[0], x1 = xp[1], x2 = xp[2];
        int r0 = lane, r1 = 32 + lane, r2 = 64 + lane, r3 = 96 + lane;
        float a0 = sb[r0] + sWih[r0*3]*x0 + sWih[r0*3+1]*x1 + sWih[r0*3+2]*x2;
        float a1 = sb[r1] + sWih[r1*3]*x0 + sWih[r1*3+1]*x1 + sWih[r1*3+2]*x2;
        float a2 = sb[r2] + sWih[r2*3]*x0 + sWih[r2*3+1]*x1 + sWih[r2*3+2]*x2;
        float a3 = sb[r3] + sWih[r3*3]*x0 + sWih[r3*3+1]*x1 + sWih[r3*3+2]*x2;
        #pragma unroll
        for (int k = 0; k < 32; k++) {
            float hk = __shfl_sync(0xffffffffu, h, k);
            const float* w = &sWhhT[k*128 + lane];
            a0 += w[0]  * hk;
            a1 += w[32] * hk;
            a2 += w[64] * hk;
            a3 += w[96] * hk;
        }
        c = sig_fast(a1) * c + sig_fast(a0) * tanh_fast(a2);
        h = sig_fast(a3) * tanh_fast(c);
        hs[((size_t)t*NN + n)*32 + lane] = h;
    }
}

// ---------------------------------------------------------------------------
// GAT layer 0 (R1 structure, __expf + reciprocal tweaks)
// ---------------------------------------------------------------------------
__global__ void gat0_kernel(const float* __restrict__ traj,
        const float* __restrict__ w0, const float* __restrict__ as0,
        const float* __restrict__ ad0, const float* __restrict__ b0)
{
    __shared__ float shp[4096];   // hp[p][h*16+o]
    __shared__ float sbuf[4096];  // w0, then attn-exp per head
    __shared__ float sx[2048];    // x[p][f]
    __shared__ float sS[256], sD[256];
    __shared__ float smean[32], sinv[32], srinv[64];
    const int tid = threadIdx.x;
    const int b = blockIdx.x, sIdx = b >> 3, tIdx = b & 7;

    for (int i = tid; i < 2048; i += 256) {
        int p = i >> 5, f = i & 31;
        sx[i] = traj[((size_t)tIdx*NN + sIdx*64 + p)*32 + f];
    }
    for (int i = tid; i < 2048; i += 256) sbuf[i] = w0[i];
    __syncthreads();

    if (tid < 32) {
        float s = 0.f, s2 = 0.f;
        for (int p = 0; p < 64; p++) { float v = sx[p*32 + tid]; s += v; s2 += v*v; }
        float m = s * (1.0f/64.0f);
        float var = s2 * (1.0f/64.0f) - m*m;
        smean[tid] = m; sinv[tid] = rsqrtf(var + 1e-5f);
    }
    __syncthreads();
    for (int i = tid; i < 2048; i += 256) { int f = i & 31; sx[i] = (sx[i] - smean[f]) * sinv[f]; }
    __syncthreads();

    for (int i = tid; i < 4096; i += 256) {
        int p = i >> 6, j = i & 63, hh = j >> 4, o = j & 15;
        const float* wp = &sbuf[hh*512 + o];
        const float* xp = &sx[p*32];
        float acc = 0.f;
        #pragma unroll
        for (int f = 0; f < 32; f++) acc += xp[f] * wp[f*16];
        shp[i] = acc;
    }
    __syncthreads();

    {
        int hh = tid >> 6, p = tid & 63;
        const float* hpp = &shp[p*64 + hh*16];
        float as = 0.f, ad = 0.f;
        #pragma unroll
        for (int o = 0; o < 16; o++) { float v = hpp[o]; as += v * as0[hh*16+o]; ad += v * ad0[hh*16+o]; }
        sS[tid] = as; sD[tid] = ad;
    }
    __syncthreads();

    for (int hh = 0; hh < 4; hh++) {
        if (tid < 64) {
            int p = tid; float sp = sS[hh*64 + p];
            float mx = -1e30f;
            for (int m = 0; m < 64; m++) { float l = sp + sD[hh*64+m]; l = (l > 0.f) ? l : 0.2f*l; mx = fmaxf(mx, l); }
            float sum = 0.f;
            for (int m = 0; m < 64; m++) {
                float l = sp + sD[hh*64+m]; l = (l > 0.f) ? l : 0.2f*l;
                float e = __expf(l - mx); sbuf[p*64 + m] = e; sum += e;
            }
            srinv[p] = 1.0f / sum;
        }
        __syncthreads();
        for (int i = tid; i < 1024; i += 256) {
            int p = i >> 4, o = i & 15;
            const float* ap = &sbuf[p*64];
            float acc = 0.f;
            #pragma unroll
            for (int m = 0; m < 64; m++) acc += ap[m] * shp[m*64 + hh*16 + o];
            float v = acc * srinv[p] + b0[o];
            v = (v > 0.f) ? v : (__expf(v) - 1.f);  // elu
            g_x2[((size_t)b*64 + p)*64 + hh*16 + o] = v;
        }
        __syncthreads();
    }
}

// ---------------------------------------------------------------------------
// GAT layer 1 (R1 structure, __expf + reciprocal tweaks)
// ---------------------------------------------------------------------------
__global__ void gat1_kernel(const float* __restrict__ w1, const float* __restrict__ as1,
        const float* __restrict__ ad1, const float* __restrict__ b1)
{
    __shared__ float sx[4096];
    __shared__ float shp[2048];
    __shared__ float sbuf[4096];
    __shared__ float sS[64], sD[64], smean[64], sinv[64], srinv[64];
    const int tid = threadIdx.x;
    const int b = blockIdx.x, sIdx = b >> 3, tIdx = b & 7;

    for (int i = tid; i < 4096; i += 256) sx[i] = g_x2[(size_t)b*4096 + i];
    __syncthreads();

    if (tid < 64) {
        float s = 0.f, s2 = 0.f;
        for (int p = 0; p < 64; p++) { float v = sx[p*64 + tid]; s += v; s2 += v*v; }
        float m = s * (1.0f/64.0f);
        float var = s2 * (1.0f/64.0f) - m*m;
        smean[tid] = m; sinv[tid] = rsqrtf(var + 1e-5f);
    }
    __syncthreads();
    for (int i = tid; i < 4096; i += 256) { int f = i & 63; sx[i] = (sx[i] - smean[f]) * sinv[f]; }
    for (int i = tid; i < 2048; i += 256) sbuf[i] = w1[i];
    __syncthreads();

    for (int i = tid; i < 2048; i += 256) {
        int p = i >> 5, o = i & 31;
        const float* xp = &sx[p*64];
        const float* wp = &sbuf[o];
        float acc = 0.f;
        #pragma unroll
        for (int f = 0; f < 64; f++) acc += xp[f] * wp[f*32];
        shp[i] = acc;
    }
    __syncthreads();

    if (tid < 64) {
        int p = tid; const float* hpp = &shp[p*32];
        float as = 0.f, ad = 0.f;
        #pragma unroll
        for (int o = 0; o < 32; o++) { float v = hpp[o]; as += v * as1[o]; ad += v * ad1[o]; }
        sS[p] = as; sD[p] = ad;
    }
    __syncthreads();

    if (tid < 64) {
        int p = tid; float sp = sS[p];
        float mx = -1e30f;
        for (int m = 0; m < 64; m++) { float l = sp + sD[m]; l = (l > 0.f) ? l : 0.2f*l; mx = fmaxf(mx, l); }
        float sum = 0.f;
        for (int m = 0; m < 64; m++) {
            float l = sp + sD[m]; l = (l > 0.f) ? l : 0.2f*l;
            float e = __expf(l - mx); sbuf[p*64 + m] = e; sum += e;
        }
        srinv[p] = 1.0f / sum;
    }
    __syncthreads();

    for (int i = tid; i < 2048; i += 256) {
        int p = i >> 5, o = i & 31;
        const float* ap = &sbuf[p*64];
        float acc = 0.f;
        #pragma unroll
        for (int m = 0; m < 64; m++) acc += ap[m] * shp[m*32 + o];
        float v = acc * srinv[p] + b1[o];
        g_graph_in[((size_t)tIdx*NN + sIdx*64 + p)*32 + o] = v;
    }
}

// ---------------------------------------------------------------------------
// Precompute x-gates for graph LSTM: g_gates[row][j] = b[j] + sum_k in[row][k]*Wih[j][k]
// rows = TT*NN. Block: 256 threads, 64 rows. Thread: 8 rows x 1 col-quad.
// ---------------------------------------------------------------------------
__global__ void gates_precompute_kernel(
        const float* __restrict__ Wih,
        const float* __restrict__ bih, const float* __restrict__ bhh)
{
    __shared__ __align__(16) float sx[2048];       // 64 rows x 32
    __shared__ __align__(16) float4 sw4[1024];     // [k][j4]: quad {Wih[4j4..4j4+3][k]}
    __shared__ __align__(16) float4 sb4[32];
    const int tid = threadIdx.x;
    const size_t row0 = (size_t)blockIdx.x * 64;

    for (int i = tid; i < 2048; i += 256) sx[i] = g_graph_in[row0*32 + i];
    for (int i = tid; i < 4096; i += 256) {
        int j = i >> 5, k = i & 31;        // Wih[j][k]
        ((float*)sw4)[(k*32 + (j >> 2))*4 + (j & 3)] = Wih[i];
    }
    if (tid < 128) ((float*)sb4)[( (tid >> 2) )*4 + (tid & 3)] = bih[tid] + bhh[tid];
    __syncthreads();

    const int j4 = tid & 31;      // lane
    const int rg = tid >> 5;      // warp -> row group of 8
    float4 acc[8];
    const float4 bb = sb4[j4];
    #pragma unroll
    for (int r = 0; r < 8; r++) acc[r] = bb;

    #pragma unroll
    for (int k = 0; k < 32; k++) {
        float4 w = sw4[k*32 + j4];
        #pragma unroll
        for (int r = 0; r < 8; r++) acc[r].x += sx[(rg*8+r)*32 + k] * w.x;
        #pragma unroll
        for (int r = 0; r < 8; r++) {
            float xv = sx[(rg*8+r)*32 + k];
            acc[r].y += xv * w.y; acc[r].z += xv * w.z; acc[r].w += xv * w.w;
        }
    }
    float4* outp = (float4*)g_gates;
    #pragma unroll
    for (int r = 0; r < 8; r++) outp[(row0 + rg*8 + r)*32 + j4] = acc[r];
}

// ---------------------------------------------------------------------------
// LSTM graph serial part: x-gates precomputed; only h recurrence here.
// Warp = 1 ped (R1 structure).
// ---------------------------------------------------------------------------
__global__ void lstm_graph_kernel(
        const float* __restrict__ h0, const float* __restrict__ c0,
        const float* __restrict__ Whh,
        float* __restrict__ hs)
{
    __shared__ float sWhhT[4096];   // [32][128] k-major
    const int tid = threadIdx.x;
    for (int i = tid; i < 4096; i += 256) { int row = i >> 5, k = i & 31; sWhhT[k*128 + row] = Whh[i]; }
    __syncthreads();

    const int lane = tid & 31;
    const int n = blockIdx.x * 8 + (tid >> 5);
    float h = h0[n*32 + lane];
    float c = c0[n*32 + lane];

    #pragma unroll
    for (int t = 0; t < TT; t++) {
        const float* gp = &g_gates[((size_t)t*NN + n)*128];
        float g0 = gp[lane], g1 = gp[32+lane], g2 = gp[64+lane], g3 = gp[96+lane];
        float a0 = 0.f, a1 = 0.f, a2 = 0.f, a3 = 0.f;
        #pragma unroll
        for (int k = 0; k < 32; k++) {
            float hk = __shfl_sync(0xffffffffu, h, k);
            const float* w = &sWhhT[k*128 + lane];
            a0 += w[0]  * hk;
            a1 += w[32] * hk;
            a2 += w[64] * hk;
            a3 += w[96] * hk;
        }
        a0 += g0; a1 += g1; a2 += g2; a3 += g3;
        c = sig_fast(a1) * c + sig_fast(a0) * tanh_fast(a2);
        h = sig_fast(a3) * tanh_fast(c);
        hs[((size_t)t*NN + n)*32 + lane] = h;
    }
}

// ---------------------------------------------------------------------------
// Concat (float4): encoded[n] = [traj_hs[7,n] | graph_hs[7,n] | z[n/64]]
// ---------------------------------------------------------------------------
__global__ void concat_kernel(const float* __restrict__ z,
        const float* __restrict__ traj, const float* __restrict__ graph,
        float* __restrict__ out)
{
    int idx = blockIdx.x * blockDim.x + threadIdx.x;
    if (idx >= NN*18) return;
    int n = idx / 18, j = idx - n*18;
    float4 v;
    if (j < 8)       v = ((const float4*)traj)[((size_t)7*NN + n)*8 + j];
    else if (j < 16) v = ((const float4*)graph)[((size_t)7*NN + n)*8 + (j - 8)];
    else             v = ((const float4*)z)[(n >> 6)*2 + (j - 16)];
    ((float4*)out)[idx] = v;
}

extern "C" void kernel_launch(void* const* d_in, const int* in_sizes, int n_in,
                              void* d_out, int out_size) {
    const float* obs  = (const float*)d_in[0];
    const float* h0t  = (const float*)d_in[1];
    const float* c0t  = (const float*)d_in[2];
    const float* h0g  = (const float*)d_in[3];
    const float* c0g  = (const float*)d_in[4];
    const float* z    = (const float*)d_in[5];
    const float* WihT = (const float*)d_in[6];
    const float* WhhT = (const float*)d_in[7];
    const float* bihT = (const float*)d_in[8];
    const float* bhhT = (const float*)d_in[9];
    const float* WihG = (const float*)d_in[10];
    const float* WhhG = (const float*)d_in[11];
    const float* bihG = (const float*)d_in[12];
    const float* bhhG = (const float*)d_in[13];
    const float* w0   = (const float*)d_in[14];
    const float* as0  = (const float*)d_in[15];
    const float* ad0  = (const float*)d_in[16];
    const float* b0   = (const float*)d_in[17];
    const float* w1   = (const float*)d_in[18];
    const float* as1  = (const float*)d_in[19];
    const float* ad1  = (const float*)d_in[20];
    const float* b1   = (const float*)d_in[21];
    float* out = (float*)d_out;

    float* traj_hs;
    float* graph_hs;
    if (out_size >= ENC_ELEMS + 2*SEQ_ELEMS) {
        graph_hs = out + ENC_ELEMS;
        traj_hs  = out + ENC_ELEMS + SEQ_ELEMS;
    } else {
        void* pt = nullptr; void* pg = nullptr;
        cudaGetSymbolAddress(&pt, g_traj_fb);
        cudaGetSymbolAddress(&pg, g_graph_fb);
        traj_hs  = (float*)pt;
        graph_hs = (float*)pg;
    }

    lstm_traj_kernel<<<NN/8, 256>>>(obs, h0t, c0t, WihT, WhhT, bihT, bhhT, traj_hs);
    gat0_kernel<<<SS*TT, 256>>>(traj_hs, w0, as0, ad0, b0);
    gat1_kernel<<<SS*TT, 256>>>(w1, as1, ad1, b1);
    gates_precompute_kernel<<<(TT*NN)/64, 256>>>(WihG, bihG, bhhG);
    lstm_graph_kernel<<<NN/8, 256>>>(h0g, c0g, WhhG, graph_hs);
    concat_kernel<<<(NN*18 + 255)/256, 256>>>(z, traj_hs, graph_hs, out);
}

// round 5
// speedup vs baseline: 1.8904x; 1.1605x over previous
#include <cuda_runtime.h>
#include <math.h>

#define SS 512
#define PP 64
#define TT 8
#define NN (SS*PP)            // 32768

#define ENC_ELEMS (NN*72)     // 2359296
#define SEQ_ELEMS (TT*NN*32)  // 8388608

__device__ float g_graph_in[SEQ_ELEMS];        // GAT output -> graph LSTM input
__device__ float g_x2[(size_t)SS*TT*64*64];    // GAT layer0 output (elu'd)
__device__ float g_traj_fb[SEQ_ELEMS];
__device__ float g_graph_fb[SEQ_ELEMS];

__device__ __forceinline__ float tanh_fast(float x){
    float y; asm("tanh.approx.f32 %0, %1;" : "=f"(y) : "f"(x)); return y;
}
__device__ __forceinline__ float sig_fast(float x){
    return 0.5f * tanh_fast(0.5f * x) + 0.5f;
}
__device__ __forceinline__ void fma4(float4& a, float s, const float4 w){
    a.x += s*w.x; a.y += s*w.y; a.z += s*w.z; a.w += s*w.w;
}

// ---------------------------------------------------------------------------
// LSTM traj: input 3, hidden 32, T=8. lane = hidden unit, 2 peds/thread.
// Whh packed float4 by gate: sWhh4[k*32+lane] = {Wi,Wf,Wg,Wo}[.,k] at row lane.
// t-loop deliberately NOT unrolled (serial dep; keeps regs low).
// ---------------------------------------------------------------------------
__global__ void lstm_traj_kernel(const float* __restrict__ x,
        const float* __restrict__ h0, const float* __restrict__ c0,
        const float* __restrict__ Wih, const float* __restrict__ Whh,
        const float* __restrict__ bih, const float* __restrict__ bhh,
        float* __restrict__ hs)
{
    __shared__ __align__(16) float4 sWhh4[1024];  // [k][lane] -> gates
    __shared__ __align__(16) float4 sWihP[96];    // [j=0..2][lane] -> gates
    __shared__ __align__(16) float4 sb4[32];
    const int tid = threadIdx.x;

    for (int i = tid; i < 4096; i += 256) {
        int r = i >> 5, k = i & 31;   // Whh[r][k]
        ((float*)sWhh4)[(k*32 + (r & 31))*4 + (r >> 5)] = Whh[i];
    }
    for (int i = tid; i < 384; i += 256) {
        int r = i / 3, j = i - r*3;
        ((float*)sWihP)[(j*32 + (r & 31))*4 + (r >> 5)] = Wih[i];
    }
    if (tid < 128) ((float*)sb4)[(tid & 31)*4 + (tid >> 5)] = bih[tid] + bhh[tid];
    __syncthreads();

    const int lane = tid & 31;
    const int n0 = blockIdx.x * 16 + (tid >> 5) * 2;

    float h0r = h0[n0*32 + lane],     c0r = c0[n0*32 + lane];
    float h1r = h0[(n0+1)*32 + lane], c1r = c0[(n0+1)*32 + lane];

    #pragma unroll 1
    for (int t = 0; t < TT; t++) {
        const float4 w0 = sWihP[lane], w1 = sWihP[32 + lane], w2 = sWihP[64 + lane];
        const float4 bb = sb4[lane];
        const float* xp0 = x + ((size_t)t*NN + n0) * 3;
        float4 a0 = bb, a1 = bb;
        fma4(a0, xp0[0], w0); fma4(a0, xp0[1], w1); fma4(a0, xp0[2], w2);
        fma4(a1, xp0[3], w0); fma4(a1, xp0[4], w1); fma4(a1, xp0[5], w2);
        #pragma unroll
        for (int k = 0; k < 32; k++) {
            float4 w = sWhh4[k*32 + lane];
            float hk0 = __shfl_sync(0xffffffffu, h0r, k);
            float hk1 = __shfl_sync(0xffffffffu, h1r, k);
            fma4(a0, hk0, w);
            fma4(a1, hk1, w);
        }
        c0r = sig_fast(a0.y) * c0r + sig_fast(a0.x) * tanh_fast(a0.z);
        h0r = sig_fast(a0.w) * tanh_fast(c0r);
        c1r = sig_fast(a1.y) * c1r + sig_fast(a1.x) * tanh_fast(a1.z);
        h1r = sig_fast(a1.w) * tanh_fast(c1r);
        hs[((size_t)t*NN + n0)*32 + lane]     = h0r;
        hs[((size_t)t*NN + n0 + 1)*32 + lane] = h1r;
    }
}

// ---------------------------------------------------------------------------
// GAT layer 0 (unchanged from R4 best)
// ---------------------------------------------------------------------------
__global__ void gat0_kernel(const float* __restrict__ traj,
        const float* __restrict__ w0, const float* __restrict__ as0,
        const float* __restrict__ ad0, const float* __restrict__ b0)
{
    __shared__ float shp[4096];   // hp[p][h*16+o]
    __shared__ float sbuf[4096];  // w0, then attn-exp per head
    __shared__ float sx[2048];    // x[p][f]
    __shared__ float sS[256], sD[256];
    __shared__ float smean[32], sinv[32], srinv[64];
    const int tid = threadIdx.x;
    const int b = blockIdx.x, sIdx = b >> 3, tIdx = b & 7;

    for (int i = tid; i < 2048; i += 256) {
        int p = i >> 5, f = i & 31;
        sx[i] = traj[((size_t)tIdx*NN + sIdx*64 + p)*32 + f];
    }
    for (int i = tid; i < 2048; i += 256) sbuf[i] = w0[i];
    __syncthreads();

    if (tid < 32) {
        float s = 0.f, s2 = 0.f;
        for (int p = 0; p < 64; p++) { float v = sx[p*32 + tid]; s += v; s2 += v*v; }
        float m = s * (1.0f/64.0f);
        float var = s2 * (1.0f/64.0f) - m*m;
        smean[tid] = m; sinv[tid] = rsqrtf(var + 1e-5f);
    }
    __syncthreads();
    for (int i = tid; i < 2048; i += 256) { int f = i & 31; sx[i] = (sx[i] - smean[f]) * sinv[f]; }
    __syncthreads();

    for (int i = tid; i < 4096; i += 256) {
        int p = i >> 6, j = i & 63, hh = j >> 4, o = j & 15;
        const float* wp = &sbuf[hh*512 + o];
        const float* xp = &sx[p*32];
        float acc = 0.f;
        #pragma unroll
        for (int f = 0; f < 32; f++) acc += xp[f] * wp[f*16];
        shp[i] = acc;
    }
    __syncthreads();

    {
        int hh = tid >> 6, p = tid & 63;
        const float* hpp = &shp[p*64 + hh*16];
        float as = 0.f, ad = 0.f;
        #pragma unroll
        for (int o = 0; o < 16; o++) { float v = hpp[o]; as += v * as0[hh*16+o]; ad += v * ad0[hh*16+o]; }
        sS[tid] = as; sD[tid] = ad;
    }
    __syncthreads();

    for (int hh = 0; hh < 4; hh++) {
        if (tid < 64) {
            int p = tid; float sp = sS[hh*64 + p];
            float mx = -1e30f;
            for (int m = 0; m < 64; m++) { float l = sp + sD[hh*64+m]; l = (l > 0.f) ? l : 0.2f*l; mx = fmaxf(mx, l); }
            float sum = 0.f;
            for (int m = 0; m < 64; m++) {
                float l = sp + sD[hh*64+m]; l = (l > 0.f) ? l : 0.2f*l;
                float e = __expf(l - mx); sbuf[p*64 + m] = e; sum += e;
            }
            srinv[p] = 1.0f / sum;
        }
        __syncthreads();
        for (int i = tid; i < 1024; i += 256) {
            int p = i >> 4, o = i & 15;
            const float* ap = &sbuf[p*64];
            float acc = 0.f;
            #pragma unroll
            for (int m = 0; m < 64; m++) acc += ap[m] * shp[m*64 + hh*16 + o];
            float v = acc * srinv[p] + b0[o];
            v = (v > 0.f) ? v : (__expf(v) - 1.f);  // elu
            g_x2[((size_t)b*64 + p)*64 + hh*16 + o] = v;
        }
        __syncthreads();
    }
}

// ---------------------------------------------------------------------------
// GAT layer 1 (unchanged from R4 best)
// ---------------------------------------------------------------------------
__global__ void gat1_kernel(const float* __restrict__ w1, const float* __restrict__ as1,
        const float* __restrict__ ad1, const float* __restrict__ b1)
{
    __shared__ float sx[4096];
    __shared__ float shp[2048];
    __shared__ float sbuf[4096];
    __shared__ float sS[64], sD[64], smean[64], sinv[64], srinv[64];
    const int tid = threadIdx.x;
    const int b = blockIdx.x, sIdx = b >> 3, tIdx = b & 7;

    for (int i = tid; i < 4096; i += 256) sx[i] = g_x2[(size_t)b*4096 + i];
    __syncthreads();

    if (tid < 64) {
        float s = 0.f, s2 = 0.f;
        for (int p = 0; p < 64; p++) { float v = sx[p*64 + tid]; s += v; s2 += v*v; }
        float m = s * (1.0f/64.0f);
        float var = s2 * (1.0f/64.0f) - m*m;
        smean[tid] = m; sinv[tid] = rsqrtf(var + 1e-5f);
    }
    __syncthreads();
    for (int i = tid; i < 4096; i += 256) { int f = i & 63; sx[i] = (sx[i] - smean[f]) * sinv[f]; }
    for (int i = tid; i < 2048; i += 256) sbuf[i] = w1[i];
    __syncthreads();

    for (int i = tid; i < 2048; i += 256) {
        int p = i >> 5, o = i & 31;
        const float* xp = &sx[p*64];
        const float* wp = &sbuf[o];
        float acc = 0.f;
        #pragma unroll
        for (int f = 0; f < 64; f++) acc += xp[f] * wp[f*32];
        shp[i] = acc;
    }
    __syncthreads();

    if (tid < 64) {
        int p = tid; const float* hpp = &shp[p*32];
        float as = 0.f, ad = 0.f;
        #pragma unroll
        for (int o = 0; o < 32; o++) { float v = hpp[o]; as += v * as1[o]; ad += v * ad1[o]; }
        sS[p] = as; sD[p] = ad;
    }
    __syncthreads();

    if (tid < 64) {
        int p = tid; float sp = sS[p];
        float mx = -1e30f;
        for (int m = 0; m < 64; m++) { float l = sp + sD[m]; l = (l > 0.f) ? l : 0.2f*l; mx = fmaxf(mx, l); }
        float sum = 0.f;
        for (int m = 0; m < 64; m++) {
            float l = sp + sD[m]; l = (l > 0.f) ? l : 0.2f*l;
            float e = __expf(l - mx); sbuf[p*64 + m] = e; sum += e;
        }
        srinv[p] = 1.0f / sum;
    }
    __syncthreads();

    for (int i = tid; i < 2048; i += 256) {
        int p = i >> 5, o = i & 31;
        const float* ap = &sbuf[p*64];
        float acc = 0.f;
        #pragma unroll
        for (int m = 0; m < 64; m++) acc += ap[m] * shp[m*32 + o];
        float v = acc * srinv[p] + b1[o];
        g_graph_in[((size_t)tIdx*NN + sIdx*64 + p)*32 + o] = v;
    }
}

// ---------------------------------------------------------------------------
// LSTM graph (fused x+h): input 32, hidden 32. 2 peds/thread, float4 weights,
// t-loop not unrolled.
// ---------------------------------------------------------------------------
__global__ void lstm_graph_kernel(
        const float* __restrict__ h0, const float* __restrict__ c0,
        const float* __restrict__ Wih, const float* __restrict__ Whh,
        const float* __restrict__ bih, const float* __restrict__ bhh,
        float* __restrict__ hs)
{
    __shared__ __align__(16) float4 sWih4[1024];  // [k][lane] -> gates
    __shared__ __align__(16) float4 sWhh4[1024];
    __shared__ __align__(16) float4 sb4[32];
    const int tid = threadIdx.x;

    for (int i = tid; i < 4096; i += 256) {
        int r = i >> 5, k = i & 31;
        int idx = (k*32 + (r & 31))*4 + (r >> 5);
        ((float*)sWih4)[idx] = Wih[i];
        ((float*)sWhh4)[idx] = Whh[i];
    }
    if (tid < 128) ((float*)sb4)[(tid & 31)*4 + (tid >> 5)] = bih[tid] + bhh[tid];
    __syncthreads();

    const int lane = tid & 31;
    const int n0 = blockIdx.x * 16 + (tid >> 5) * 2;

    float h0r = h0[n0*32 + lane],     c0r = c0[n0*32 + lane];
    float h1r = h0[(n0+1)*32 + lane], c1r = c0[(n0+1)*32 + lane];

    #pragma unroll 1
    for (int t = 0; t < TT; t++) {
        const float4 bb = sb4[lane];
        float x0v = g_graph_in[((size_t)t*NN + n0)*32 + lane];
        float x1v = g_graph_in[((size_t)t*NN + n0 + 1)*32 + lane];
        float4 a0 = bb, a1 = bb;
        #pragma unroll
        for (int k = 0; k < 32; k++) {
            float4 wi = sWih4[k*32 + lane];
            float4 wh = sWhh4[k*32 + lane];
            float xk0 = __shfl_sync(0xffffffffu, x0v, k);
            float hk0 = __shfl_sync(0xffffffffu, h0r, k);
            float xk1 = __shfl_sync(0xffffffffu, x1v, k);
            float hk1 = __shfl_sync(0xffffffffu, h1r, k);
            fma4(a0, xk0, wi); fma4(a0, hk0, wh);
            fma4(a1, xk1, wi); fma4(a1, hk1, wh);
        }
        c0r = sig_fast(a0.y) * c0r + sig_fast(a0.x) * tanh_fast(a0.z);
        h0r = sig_fast(a0.w) * tanh_fast(c0r);
        c1r = sig_fast(a1.y) * c1r + sig_fast(a1.x) * tanh_fast(a1.z);
        h1r = sig_fast(a1.w) * tanh_fast(c1r);
        hs[((size_t)t*NN + n0)*32 + lane]     = h0r;
        hs[((size_t)t*NN + n0 + 1)*32 + lane] = h1r;
    }
}

// ---------------------------------------------------------------------------
// Concat (float4): encoded[n] = [traj_hs[7,n] | graph_hs[7,n] | z[n/64]]
// ---------------------------------------------------------------------------
__global__ void concat_kernel(const float* __restrict__ z,
        const float* __restrict__ traj, const float* __restrict__ graph,
        float* __restrict__ out)
{
    int idx = blockIdx.x * blockDim.x + threadIdx.x;
    if (idx >= NN*18) return;
    int n = idx / 18, j = idx - n*18;
    float4 v;
    if (j < 8)       v = ((const float4*)traj)[((size_t)7*NN + n)*8 + j];
    else if (j < 16) v = ((const float4*)graph)[((size_t)7*NN + n)*8 + (j - 8)];
    else             v = ((const float4*)z)[(n >> 6)*2 + (j - 16)];
    ((float4*)out)[idx] = v;
}

extern "C" void kernel_launch(void* const* d_in, const int* in_sizes, int n_in,
                              void* d_out, int out_size) {
    const float* obs  = (const float*)d_in[0];
    const float* h0t  = (const float*)d_in[1];
    const float* c0t  = (const float*)d_in[2];
    const float* h0g  = (const float*)d_in[3];
    const float* c0g  = (const float*)d_in[4];
    const float* z    = (const float*)d_in[5];
    const float* WihT = (const float*)d_in[6];
    const float* WhhT = (const float*)d_in[7];
    const float* bihT = (const float*)d_in[8];
    const float* bhhT = (const float*)d_in[9];
    const float* WihG = (const float*)d_in[10];
    const float* WhhG = (const float*)d_in[11];
    const float* bihG = (const float*)d_in[12];
    const float* bhhG = (const float*)d_in[13];
    const float* w0   = (const float*)d_in[14];
    const float* as0  = (const float*)d_in[15];
    const float* ad0  = (const float*)d_in[16];
    const float* b0   = (const float*)d_in[17];
    const float* w1   = (const float*)d_in[18];
    const float* as1  = (const float*)d_in[19];
    const float* ad1  = (const float*)d_in[20];
    const float* b1   = (const float*)d_in[21];
    float* out = (float*)d_out;

    float* traj_hs;
    float* graph_hs;
    if (out_size >= ENC_ELEMS + 2*SEQ_ELEMS) {
        graph_hs = out + ENC_ELEMS;
        traj_hs  = out + ENC_ELEMS + SEQ_ELEMS;
    } else {
        void* pt = nullptr; void* pg = nullptr;
        cudaGetSymbolAddress(&pt, g_traj_fb);
        cudaGetSymbolAddress(&pg, g_graph_fb);
        traj_hs  = (float*)pt;
        graph_hs = (float*)pg;
    }

    lstm_traj_kernel<<<NN/16, 256>>>(obs, h0t, c0t, WihT, WhhT, bihT, bhhT, traj_hs);
    gat0_kernel<<<SS*TT, 256>>>(traj_hs, w0, as0, ad0, b0);
    gat1_kernel<<<SS*TT, 256>>>(w1, as1, ad1, b1);
    lstm_graph_kernel<<<NN/16, 256>>>(h0g, c0g, WihG, WhhG, bihG, bhhG, graph_hs);
    concat_kernel<<<(NN*18 + 255)/256, 256>>>(z, traj_hs, graph_hs, out);
}

// round 7
// speedup vs baseline: 2.1147x; 1.1187x over previous
#include <cuda_runtime.h>
#include <math.h>

#define SS 512
#define PP 64
#define TT 8
#define NN (SS*PP)            // 32768

#define ENC_ELEMS (NN*72)     // 2359296
#define SEQ_ELEMS (TT*NN*32)  // 8388608

__device__ float g_graph_in[SEQ_ELEMS];        // GAT output -> graph LSTM input
__device__ float g_x2[(size_t)SS*TT*64*64];    // GAT layer0 output (elu'd)
__device__ float g_traj_fb[SEQ_ELEMS];
__device__ float g_graph_fb[SEQ_ELEMS];

__device__ __forceinline__ float tanh_fast(float x){
    float y; asm("tanh.approx.f32 %0, %1;" : "=f"(y) : "f"(x)); return y;
}
__device__ __forceinline__ float sig_fast(float x){
    return 0.5f * tanh_fast(0.5f * x) + 0.5f;
}
__device__ __forceinline__ void fma4(float4& a, float s, const float4 w){
    a.x += s*w.x; a.y += s*w.y; a.z += s*w.z; a.w += s*w.w;
}

// ---------------------------------------------------------------------------
// LSTM traj: input 3, hidden 32, T=8. lane = hidden unit, 4 peds/thread.
// Whh packed float4 by gate: sWhh4[k*32+lane] = {Wi,Wf,Wg,Wo}[.,k] at row lane.
// t-loop NOT unrolled (serial dep; keeps regs low).
// ---------------------------------------------------------------------------
__global__ void lstm_traj_kernel(const float* __restrict__ x,
        const float* __restrict__ h0, const float* __restrict__ c0,
        const float* __restrict__ Wih, const float* __restrict__ Whh,
        const float* __restrict__ bih, const float* __restrict__ bhh,
        float* __restrict__ hs)
{
    __shared__ __align__(16) float4 sWhh4[1024];  // [k][lane] -> gates
    __shared__ __align__(16) float4 sWihP[96];    // [j=0..2][lane] -> gates
    __shared__ __align__(16) float4 sb4[32];
    const int tid = threadIdx.x;

    for (int i = tid; i < 4096; i += 256) {
        int r = i >> 5, k = i & 31;   // Whh[r][k]
        ((float*)sWhh4)[(k*32 + (r & 31))*4 + (r >> 5)] = Whh[i];
    }
    for (int i = tid; i < 384; i += 256) {
        int r = i / 3, j = i - r*3;
        ((float*)sWihP)[(j*32 + (r & 31))*4 + (r >> 5)] = Wih[i];
    }
    if (tid < 128) ((float*)sb4)[(tid & 31)*4 + (tid >> 5)] = bih[tid] + bhh[tid];
    __syncthreads();

    const int lane = tid & 31;
    const int n0 = blockIdx.x * 32 + (tid >> 5) * 4;

    float h[4], c[4];
    #pragma unroll
    for (int r = 0; r < 4; r++) { h[r] = h0[(n0+r)*32 + lane]; c[r] = c0[(n0+r)*32 + lane]; }

    #pragma unroll 1
    for (int t = 0; t < TT; t++) {
        const float4 w0 = sWihP[lane], w1 = sWihP[32 + lane], w2 = sWihP[64 + lane];
        const float4 bb = sb4[lane];
        const float* xp = x + ((size_t)t*NN + n0) * 3;
        float4 a[4];
        #pragma unroll
        for (int r = 0; r < 4; r++) {
            a[r] = bb;
            fma4(a[r], xp[r*3+0], w0); fma4(a[r], xp[r*3+1], w1); fma4(a[r], xp[r*3+2], w2);
        }
        #pragma unroll
        for (int k = 0; k < 32; k++) {
            float4 w = sWhh4[k*32 + lane];
            #pragma unroll
            for (int r = 0; r < 4; r++) {
                float hk = __shfl_sync(0xffffffffu, h[r], k);
                fma4(a[r], hk, w);
            }
        }
        #pragma unroll
        for (int r = 0; r < 4; r++) {
            c[r] = sig_fast(a[r].y) * c[r] + sig_fast(a[r].x) * tanh_fast(a[r].z);
            h[r] = sig_fast(a[r].w) * tanh_fast(c[r]);
            hs[((size_t)t*NN + n0 + r)*32 + lane] = h[r];
        }
    }
}

// ---------------------------------------------------------------------------
// GAT layer 0 (unchanged — measured-good)
// ---------------------------------------------------------------------------
__global__ void gat0_kernel(const float* __restrict__ traj,
        const float* __restrict__ w0, const float* __restrict__ as0,
        const float* __restrict__ ad0, const float* __restrict__ b0)
{
    __shared__ float shp[4096];   // hp[p][h*16+o]
    __shared__ float sbuf[4096];  // w0, then attn-exp per head
    __shared__ float sx[2048];    // x[p][f]
    __shared__ float sS[256], sD[256];
    __shared__ float smean[32], sinv[32], srinv[64];
    const int tid = threadIdx.x;
    const int b = blockIdx.x, sIdx = b >> 3, tIdx = b & 7;

    for (int i = tid; i < 2048; i += 256) {
        int p = i >> 5, f = i & 31;
        sx[i] = traj[((size_t)tIdx*NN + sIdx*64 + p)*32 + f];
    }
    for (int i = tid; i < 2048; i += 256) sbuf[i] = w0[i];
    __syncthreads();

    if (tid < 32) {
        float s = 0.f, s2 = 0.f;
        for (int p = 0; p < 64; p++) { float v = sx[p*32 + tid]; s += v; s2 += v*v; }
        float m = s * (1.0f/64.0f);
        float var = s2 * (1.0f/64.0f) - m*m;
        smean[tid] = m; sinv[tid] = rsqrtf(var + 1e-5f);
    }
    __syncthreads();
    for (int i = tid; i < 2048; i += 256) { int f = i & 31; sx[i] = (sx[i] - smean[f]) * sinv[f]; }
    __syncthreads();

    for (int i = tid; i < 4096; i += 256) {
        int p = i >> 6, j = i & 63, hh = j >> 4, o = j & 15;
        const float* wp = &sbuf[hh*512 + o];
        const float* xp = &sx[p*32];
        float acc = 0.f;
        #pragma unroll
        for (int f = 0; f < 32; f++) acc += xp[f] * wp[f*16];
        shp[i] = acc;
    }
    __syncthreads();

    {
        int hh = tid >> 6, p = tid & 63;
        const float* hpp = &shp[p*64 + hh*16];
        float as = 0.f, ad = 0.f;
        #pragma unroll
        for (int o = 0; o < 16; o++) { float v = hpp[o]; as += v * as0[hh*16+o]; ad += v * ad0[hh*16+o]; }
        sS[tid] = as; sD[tid] = ad;
    }
    __syncthreads();

    for (int hh = 0; hh < 4; hh++) {
        if (tid < 64) {
            int p = tid; float sp = sS[hh*64 + p];
            float mx = -1e30f;
            for (int m = 0; m < 64; m++) { float l = sp + sD[hh*64+m]; l = (l > 0.f) ? l : 0.2f*l; mx = fmaxf(mx, l); }
            float sum = 0.f;
            for (int m = 0; m < 64; m++) {
                float l = sp + sD[hh*64+m]; l = (l > 0.f) ? l : 0.2f*l;
                float e = __expf(l - mx); sbuf[p*64 + m] = e; sum += e;
            }
            srinv[p] = 1.0f / sum;
        }
        __syncthreads();
        for (int i = tid; i < 1024; i += 256) {
            int p = i >> 4, o = i & 15;
            const float* ap = &sbuf[p*64];
            float acc = 0.f;
            #pragma unroll
            for (int m = 0; m < 64; m++) acc += ap[m] * shp[m*64 + hh*16 + o];
            float v = acc * srinv[p] + b0[o];
            v = (v > 0.f) ? v : (__expf(v) - 1.f);  // elu
            g_x2[((size_t)b*64 + p)*64 + hh*16 + o] = v;
        }
        __syncthreads();
    }
}

// ---------------------------------------------------------------------------
// GAT layer 1 (unchanged — measured-good)
// ---------------------------------------------------------------------------
__global__ void gat1_kernel(const float* __restrict__ w1, const float* __restrict__ as1,
        const float* __restrict__ ad1, const float* __restrict__ b1)
{
    __shared__ float sx[4096];
    __shared__ float shp[2048];
    __shared__ float sbuf[4096];
    __shared__ float sS[64], sD[64], smean[64], sinv[64], srinv[64];
    const int tid = threadIdx.x;
    const int b = blockIdx.x, sIdx = b >> 3, tIdx = b & 7;

    for (int i = tid; i < 4096; i += 256) sx[i] = g_x2[(size_t)b*4096 + i];
    __syncthreads();

    if (tid < 64) {
        float s = 0.f, s2 = 0.f;
        for (int p = 0; p < 64; p++) { float v = sx[p*64 + tid]; s += v; s2 += v*v; }
        float m = s * (1.0f/64.0f);
        float var = s2 * (1.0f/64.0f) - m*m;
        smean[tid] = m; sinv[tid] = rsqrtf(var + 1e-5f);
    }
    __syncthreads();
    for (int i = tid; i < 4096; i += 256) { int f = i & 63; sx[i] = (sx[i] - smean[f]) * sinv[f]; }
    for (int i = tid; i < 2048; i += 256) sbuf[i] = w1[i];
    __syncthreads();

    for (int i = tid; i < 2048; i += 256) {
        int p = i >> 5, o = i & 31;
        const float* xp = &sx[p*64];
        const float* wp = &sbuf[o];
        float acc = 0.f;
        #pragma unroll
        for (int f = 0; f < 64; f++) acc += xp[f] * wp[f*32];
        shp[i] = acc;
    }
    __syncthreads();

    if (tid < 64) {
        int p = tid; const float* hpp = &shp[p*32];
        float as = 0.f, ad = 0.f;
        #pragma unroll
        for (int o = 0; o < 32; o++) { float v = hpp[o]; as += v * as1[o]; ad += v * ad1[o]; }
        sS[p] = as; sD[p] = ad;
    }
    __syncthreads();

    if (tid < 64) {
        int p = tid; float sp = sS[p];
        float mx = -1e30f;
        for (int m = 0; m < 64; m++) { float l = sp + sD[m]; l = (l > 0.f) ? l : 0.2f*l; mx = fmaxf(mx, l); }
        float sum = 0.f;
        for (int m = 0; m < 64; m++) {
            float l = sp + sD[m]; l = (l > 0.f) ? l : 0.2f*l;
            float e = __expf(l - mx); sbuf[p*64 + m] = e; sum += e;
        }
        srinv[p] = 1.0f / sum;
    }
    __syncthreads();

    for (int i = tid; i < 2048; i += 256) {
        int p = i >> 5, o = i & 31;
        const float* ap = &sbuf[p*64];
        float acc = 0.f;
        #pragma unroll
        for (int m = 0; m < 64; m++) acc += ap[m] * shp[m*32 + o];
        float v = acc * srinv[p] + b1[o];
        g_graph_in[((size_t)tIdx*NN + sIdx*64 + p)*32 + o] = v;
    }
}

// ---------------------------------------------------------------------------
// LSTM graph (fused x+h): input 32, hidden 32. 4 peds/thread, float4 weights,
// t-loop not unrolled.
// ---------------------------------------------------------------------------
__global__ void lstm_graph_kernel(
        const float* __restrict__ h0, const float* __restrict__ c0,
        const float* __restrict__ Wih, const float* __restrict__ Whh,
        const float* __restrict__ bih, const float* __restrict__ bhh,
        float* __restrict__ hs)
{
    __shared__ __align__(16) float4 sWih4[1024];  // [k][lane] -> gates
    __shared__ __align__(16) float4 sWhh4[1024];
    __shared__ __align__(16) float4 sb4[32];
    const int tid = threadIdx.x;

    for (int i = tid; i < 4096; i += 256) {
        int r = i >> 5, k = i & 31;
        int idx = (k*32 + (r & 31))*4 + (r >> 5);
        ((float*)sWih4)[idx] = Wih[i];
        ((float*)sWhh4)[idx] = Whh[i];
    }
    if (tid < 128) ((float*)sb4)[(tid & 31)*4 + (tid >> 5)] = bih[tid] + bhh[tid];
    __syncthreads();

    const int lane = tid & 31;
    const int n0 = blockIdx.x * 32 + (tid >> 5) * 4;

    float h[4], c[4];
    #pragma unroll
    for (int r = 0; r < 4; r++) { h[r] = h0[(n0+r)*32 + lane]; c[r] = c0[(n0+r)*32 + lane]; }

    #pragma unroll 1
    for (int t = 0; t < TT; t++) {
        const float4 bb = sb4[lane];
        float xv[4];
        float4 a[4];
        #pragma unroll
        for (int r = 0; r < 4; r++) {
            xv[r] = g_graph_in[((size_t)t*NN + n0 + r)*32 + lane];
            a[r] = bb;
        }
        #pragma unroll
        for (int k = 0; k < 32; k++) {
            float4 wi = sWih4[k*32 + lane];
            float4 wh = sWhh4[k*32 + lane];
            #pragma unroll
            for (int r = 0; r < 4; r++) {
                float xk = __shfl_sync(0xffffffffu, xv[r], k);
                float hk = __shfl_sync(0xffffffffu, h[r],  k);
                fma4(a[r], xk, wi);
                fma4(a[r], hk, wh);
            }
        }
        #pragma unroll
        for (int r = 0; r < 4; r++) {
            c[r] = sig_fast(a[r].y) * c[r] + sig_fast(a[r].x) * tanh_fast(a[r].z);
            h[r] = sig_fast(a[r].w) * tanh_fast(c[r]);
            hs[((size_t)t*NN + n0 + r)*32 + lane] = h[r];
        }
    }
}

// ---------------------------------------------------------------------------
// Concat (float4): encoded[n] = [traj_hs[7,n] | graph_hs[7,n] | z[n/64]]
// ---------------------------------------------------------------------------
__global__ void concat_kernel(const float* __restrict__ z,
        const float* __restrict__ traj, const float* __restrict__ graph,
        float* __restrict__ out)
{
    int idx = blockIdx.x * blockDim.x + threadIdx.x;
    if (idx >= NN*18) return;
    int n = idx / 18, j = idx - n*18;
    float4 v;
    if (j < 8)       v = ((const float4*)traj)[((size_t)7*NN + n)*8 + j];
    else if (j < 16) v = ((const float4*)graph)[((size_t)7*NN + n)*8 + (j - 8)];
    else             v = ((const float4*)z)[(n >> 6)*2 + (j - 16)];
    ((float4*)out)[idx] = v;
}

extern "C" void kernel_launch(void* const* d_in, const int* in_sizes, int n_in,
                              void* d_out, int out_size) {
    const float* obs  = (const float*)d_in[0];
    const float* h0t  = (const float*)d_in[1];
    const float* c0t  = (const float*)d_in[2];
    const float* h0g  = (const float*)d_in[3];
    const float* c0g  = (const float*)d_in[4];
    const float* z    = (const float*)d_in[5];
    const float* WihT = (const float*)d_in[6];
    const float* WhhT = (const float*)d_in[7];
    const float* bihT = (const float*)d_in[8];
    const float* bhhT = (const float*)d_in[9];
    const float* WihG = (const float*)d_in[10];
    const float* WhhG = (const float*)d_in[11];
    const float* bihG = (const float*)d_in[12];
    const float* bhhG = (const float*)d_in[13];
    const float* w0   = (const float*)d_in[14];
    const float* as0  = (const float*)d_in[15];
    const float* ad0  = (const float*)d_in[16];
    const float* b0   = (const float*)d_in[17];
    const float* w1   = (const float*)d_in[18];
    const float* as1  = (const float*)d_in[19];
    const float* ad1  = (const float*)d_in[20];
    const float* b1   = (const float*)d_in[21];
    float* out = (float*)d_out;

    float* traj_hs;
    float* graph_hs;
    if (out_size >= ENC_ELEMS + 2*SEQ_ELEMS) {
        graph_hs = out + ENC_ELEMS;
        traj_hs  = out + ENC_ELEMS + SEQ_ELEMS;
    } else {
        void* pt = nullptr; void* pg = nullptr;
        cudaGetSymbolAddress(&pt, g_traj_fb);
        cudaGetSymbolAddress(&pg, g_graph_fb);
        traj_hs  = (float*)pt;
        graph_hs = (float*)pg;
    }

    lstm_traj_kernel<<<NN/32, 256>>>(obs, h0t, c0t, WihT, WhhT, bihT, bhhT, traj_hs);
    gat0_kernel<<<SS*TT, 256>>>(traj_hs, w0, as0, ad0, b0);
    gat1_kernel<<<SS*TT, 256>>>(w1, as1, ad1, b1);
    lstm_graph_kernel<<<NN/32, 256>>>(h0g, c0g, WihG, WhhG, bihG, bhhG, graph_hs);
    concat_kernel<<<(NN*18 + 255)/256, 256>>>(z, traj_hs, graph_hs, out);
}

// round 8
// speedup vs baseline: 2.4462x; 1.1568x over previous
#include <cuda_runtime.h>
#include <math.h>

#define SS 512
#define PP 64
#define TT 8
#define NN (SS*PP)            // 32768

#define ENC_ELEMS (NN*72)     // 2359296
#define SEQ_ELEMS (TT*NN*32)  // 8388608

__device__ float g_graph_in[SEQ_ELEMS];        // GAT output -> graph LSTM input
__device__ float g_x2[(size_t)SS*TT*64*64];    // GAT layer0 output (elu'd)
__device__ float g_traj_fb[SEQ_ELEMS];
__device__ float g_graph_fb[SEQ_ELEMS];

__device__ __forceinline__ float tanh_fast(float x){
    float y; asm("tanh.approx.f32 %0, %1;" : "=f"(y) : "f"(x)); return y;
}
__device__ __forceinline__ float sig_fast(float x){
    return 0.5f * tanh_fast(0.5f * x) + 0.5f;
}
__device__ __forceinline__ void fma4(float4& a, float s, const float4 w){
    a.x += s*w.x; a.y += s*w.y; a.z += s*w.z; a.w += s*w.w;
}

// ---------------------------------------------------------------------------
// LSTM traj: input 3, hidden 32, T=8. lane = hidden unit, 4 peds/thread.
// (unchanged from R7 — measured good)
// ---------------------------------------------------------------------------
__global__ void lstm_traj_kernel(const float* __restrict__ x,
        const float* __restrict__ h0, const float* __restrict__ c0,
        const float* __restrict__ Wih, const float* __restrict__ Whh,
        const float* __restrict__ bih, const float* __restrict__ bhh,
        float* __restrict__ hs)
{
    __shared__ __align__(16) float4 sWhh4[1024];  // [k][lane] -> gates
    __shared__ __align__(16) float4 sWihP[96];    // [j=0..2][lane] -> gates
    __shared__ __align__(16) float4 sb4[32];
    const int tid = threadIdx.x;

    for (int i = tid; i < 4096; i += 256) {
        int r = i >> 5, k = i & 31;   // Whh[r][k]
        ((float*)sWhh4)[(k*32 + (r & 31))*4 + (r >> 5)] = Whh[i];
    }
    for (int i = tid; i < 384; i += 256) {
        int r = i / 3, j = i - r*3;
        ((float*)sWihP)[(j*32 + (r & 31))*4 + (r >> 5)] = Wih[i];
    }
    if (tid < 128) ((float*)sb4)[(tid & 31)*4 + (tid >> 5)] = bih[tid] + bhh[tid];
    __syncthreads();

    const int lane = tid & 31;
    const int n0 = blockIdx.x * 32 + (tid >> 5) * 4;

    float h[4], c[4];
    #pragma unroll
    for (int r = 0; r < 4; r++) { h[r] = h0[(n0+r)*32 + lane]; c[r] = c0[(n0+r)*32 + lane]; }

    #pragma unroll 1
    for (int t = 0; t < TT; t++) {
        const float4 w0 = sWihP[lane], w1 = sWihP[32 + lane], w2 = sWihP[64 + lane];
        const float4 bb = sb4[lane];
        const float* xp = x + ((size_t)t*NN + n0) * 3;
        float4 a[4];
        #pragma unroll
        for (int r = 0; r < 4; r++) {
            a[r] = bb;
            fma4(a[r], xp[r*3+0], w0); fma4(a[r], xp[r*3+1], w1); fma4(a[r], xp[r*3+2], w2);
        }
        #pragma unroll
        for (int k = 0; k < 32; k++) {
            float4 w = sWhh4[k*32 + lane];
            #pragma unroll
            for (int r = 0; r < 4; r++) {
                float hk = __shfl_sync(0xffffffffu, h[r], k);
                fma4(a[r], hk, w);
            }
        }
        #pragma unroll
        for (int r = 0; r < 4; r++) {
            c[r] = sig_fast(a[r].y) * c[r] + sig_fast(a[r].x) * tanh_fast(a[r].z);
            h[r] = sig_fast(a[r].w) * tanh_fast(c[r]);
            hs[((size_t)t*NN + n0 + r)*32 + lane] = h[r];
        }
    }
}

// ---------------------------------------------------------------------------
// GAT layer 0: float4 matmuls + parallel softmax (R2-style, verified correct)
// ---------------------------------------------------------------------------
__global__ void gat0_kernel(const float* __restrict__ traj,
        const float* __restrict__ w0, const float* __restrict__ as0,
        const float* __restrict__ ad0, const float* __restrict__ b0)
{
    __shared__ __align__(16) float pool[4096];  // [0:2048)=x, [2048:4096)=w; later attn[64][64]
    __shared__ __align__(16) float shp[4096];   // hp[p][h*16+o]
    __shared__ float sS[256], sD[256];
    __shared__ __align__(16) float smean[32], sinv[32];
    __shared__ float srinv[64];
    __shared__ float sas[64], sad[64];
    __shared__ __align__(16) float4 sb0v[4];

    float4* sx4 = (float4*)pool;            // 512 float4
    float4* sw4 = (float4*)(pool + 2048);   // 512 float4: w(h,f,o4) at h*128+f*4+o4
    const int tid = threadIdx.x;
    const int b = blockIdx.x, sIdx = b >> 3, tIdx = b & 7;

    {
        const float4* src = (const float4*)(traj + ((size_t)tIdx*NN + sIdx*64) * 32);
        for (int i = tid; i < 512; i += 256) sx4[i] = src[i];
        const float4* wsrc = (const float4*)w0;
        for (int i = tid; i < 512; i += 256) sw4[i] = wsrc[i];
        if (tid < 64) { sas[tid] = as0[tid]; sad[tid] = ad0[tid]; }
        if (tid < 4)  sb0v[tid] = ((const float4*)b0)[tid];
    }
    __syncthreads();

    // instance norm stats over p per feature
    if (tid < 32) {
        const float* xs = pool;
        float s = 0.f, s2 = 0.f;
        for (int p = 0; p < 64; p++) { float v = xs[p*32 + tid]; s += v; s2 += v*v; }
        float m = s * (1.0f/64.0f);
        float var = s2 * (1.0f/64.0f) - m*m;
        smean[tid] = m; sinv[tid] = rsqrtf(var + 1e-5f);
    }
    __syncthreads();
    for (int i = tid; i < 512; i += 256) {
        int f4 = i & 7;
        float4 m4 = ((float4*)smean)[f4], i4 = ((float4*)sinv)[f4];
        float4 v = sx4[i];
        v.x = (v.x - m4.x)*i4.x; v.y = (v.y - m4.y)*i4.y;
        v.z = (v.z - m4.z)*i4.z; v.w = (v.w - m4.w)*i4.w;
        sx4[i] = v;
    }
    __syncthreads();

    // hp[p][hh*16 + o4*4 + e] : 1024 quads of 4 outputs
    for (int it = tid; it < 1024; it += 256) {
        int p = it >> 4, j = it & 15, hh = j >> 2, o4 = j & 3;
        float4 acc = {0.f,0.f,0.f,0.f};
        #pragma unroll
        for (int f4 = 0; f4 < 8; f4++) {
            float4 xv = sx4[p*8 + f4];
            fma4(acc, xv.x, sw4[hh*128 + (f4*4+0)*4 + o4]);
            fma4(acc, xv.y, sw4[hh*128 + (f4*4+1)*4 + o4]);
            fma4(acc, xv.z, sw4[hh*128 + (f4*4+2)*4 + o4]);
            fma4(acc, xv.w, sw4[hh*128 + (f4*4+3)*4 + o4]);
        }
        ((float4*)shp)[p*16 + hh*4 + o4] = acc;
    }
    __syncthreads();

    // s[h][p], d[h][p]
    {
        int hh = tid >> 6, p = tid & 63;
        const float4* hp4 = (const float4*)shp;
        float as = 0.f, ad = 0.f;
        #pragma unroll
        for (int o4 = 0; o4 < 4; o4++) {
            float4 v = hp4[p*16 + hh*4 + o4];
            int ob = hh*16 + o4*4;
            as += v.x*sas[ob] + v.y*sas[ob+1] + v.z*sas[ob+2] + v.w*sas[ob+3];
            ad += v.x*sad[ob] + v.y*sad[ob+1] + v.z*sad[ob+2] + v.w*sad[ob+3];
        }
        sS[tid] = as; sD[tid] = ad;
    }
    __syncthreads();

    float* sattn = pool;  // [64][64], overlays x+w (both dead)

    for (int hh = 0; hh < 4; hh++) {
        // softmax: 4 threads per row
        {
            int p = tid >> 2, q = tid & 3;
            float sp = sS[hh*64 + p];
            float l[16]; float mx = -1e30f;
            #pragma unroll
            for (int mm = 0; mm < 16; mm++) {
                float v = sp + sD[hh*64 + q*16 + mm];
                v = (v > 0.f) ? v : 0.2f*v;
                l[mm] = v; mx = fmaxf(mx, v);
            }
            mx = fmaxf(mx, __shfl_xor_sync(0xffffffffu, mx, 1));
            mx = fmaxf(mx, __shfl_xor_sync(0xffffffffu, mx, 2));
            float sum = 0.f;
            #pragma unroll
            for (int mm = 0; mm < 16; mm++) {
                float e = __expf(l[mm] - mx);
                sattn[p*64 + q*16 + mm] = e; sum += e;
            }
            sum += __shfl_xor_sync(0xffffffffu, sum, 1);
            sum += __shfl_xor_sync(0xffffffffu, sum, 2);
            if (q == 0) srinv[p] = 1.0f / sum;
        }
        __syncthreads();
        // apply: thread = (p, o4)
        {
            int p = tid >> 2, o4 = tid & 3;
            const float* ap = &sattn[p*64];
            const float4* hp4 = (const float4*)shp;
            float4 acc = {0.f,0.f,0.f,0.f};
            #pragma unroll
            for (int m = 0; m < 64; m++) fma4(acc, ap[m], hp4[m*16 + hh*4 + o4]);
            float ri = srinv[p];
            float4 bb = sb0v[o4];
            float4 res;
            res.x = acc.x*ri + bb.x; res.y = acc.y*ri + bb.y;
            res.z = acc.z*ri + bb.z; res.w = acc.w*ri + bb.w;
            res.x = (res.x > 0.f) ? res.x : (__expf(res.x) - 1.f);
            res.y = (res.y > 0.f) ? res.y : (__expf(res.y) - 1.f);
            res.z = (res.z > 0.f) ? res.z : (__expf(res.z) - 1.f);
            res.w = (res.w > 0.f) ? res.w : (__expf(res.w) - 1.f);
            ((float4*)g_x2)[((size_t)b*64 + p)*16 + hh*4 + o4] = res;
        }
        __syncthreads();
    }
}

// ---------------------------------------------------------------------------
// GAT layer 1: float4 matmuls + parallel softmax (R2-style, verified correct)
// ---------------------------------------------------------------------------
__global__ void gat1_kernel(const float* __restrict__ w1, const float* __restrict__ as1,
        const float* __restrict__ ad1, const float* __restrict__ b1)
{
    __shared__ __align__(16) float pool[4096];  // sx / sattn
    __shared__ __align__(16) float sw[2048];    // w(f,o4) at f*8+o4 (float4)
    __shared__ __align__(16) float shp[2048];
    __shared__ float sS[64], sD[64];
    __shared__ __align__(16) float smean[64], sinv[64];
    __shared__ float srinv[64], sas[32], sad[32];
    __shared__ __align__(16) float4 sb1v[8];

    float4* sx4 = (float4*)pool;          // 1024 float4
    float4* sw4 = (float4*)sw;            // 512 float4
    const int tid = threadIdx.x;
    const int b = blockIdx.x, sIdx = b >> 3, tIdx = b & 7;

    {
        const float4* src = (const float4*)(g_x2 + (size_t)b*4096);
        for (int i = tid; i < 1024; i += 256) sx4[i] = src[i];
        const float4* wsrc = (const float4*)w1;
        for (int i = tid; i < 512; i += 256) sw4[i] = wsrc[i];
        if (tid < 32) { sas[tid] = as1[tid]; sad[tid] = ad1[tid]; }
        if (tid < 8)  sb1v[tid] = ((const float4*)b1)[tid];
    }
    __syncthreads();

    if (tid < 64) {
        float s = 0.f, s2 = 0.f;
        for (int p = 0; p < 64; p++) { float v = pool[p*64 + tid]; s += v; s2 += v*v; }
        float m = s * (1.0f/64.0f);
        float var = s2 * (1.0f/64.0f) - m*m;
        smean[tid] = m; sinv[tid] = rsqrtf(var + 1e-5f);
    }
    __syncthreads();
    for (int i = tid; i < 1024; i += 256) {
        int f4 = i & 15;
        float4 m4 = ((float4*)smean)[f4], i4 = ((float4*)sinv)[f4];
        float4 v = sx4[i];
        v.x = (v.x - m4.x)*i4.x; v.y = (v.y - m4.y)*i4.y;
        v.z = (v.z - m4.z)*i4.z; v.w = (v.w - m4.w)*i4.w;
        sx4[i] = v;
    }
    __syncthreads();

    // hp: 512 quads (p, o4), 2 per thread
    for (int it = tid; it < 512; it += 256) {
        int p = it >> 3, o4 = it & 7;
        float4 acc = {0.f,0.f,0.f,0.f};
        #pragma unroll
        for (int f4 = 0; f4 < 16; f4++) {
            float4 xv = sx4[p*16 + f4];
            fma4(acc, xv.x, sw4[(f4*4+0)*8 + o4]);
            fma4(acc, xv.y, sw4[(f4*4+1)*8 + o4]);
            fma4(acc, xv.z, sw4[(f4*4+2)*8 + o4]);
            fma4(acc, xv.w, sw4[(f4*4+3)*8 + o4]);
        }
        ((float4*)shp)[p*8 + o4] = acc;
    }
    __syncthreads();

    if (tid < 64) {
        int p = tid;
        const float4* hp4 = (const float4*)shp;
        float as = 0.f, ad = 0.f;
        #pragma unroll
        for (int o4 = 0; o4 < 8; o4++) {
            float4 v = hp4[p*8 + o4];
            as += v.x*sas[o4*4] + v.y*sas[o4*4+1] + v.z*sas[o4*4+2] + v.w*sas[o4*4+3];
            ad += v.x*sad[o4*4] + v.y*sad[o4*4+1] + v.z*sad[o4*4+2] + v.w*sad[o4*4+3];
        }
        sS[p] = as; sD[p] = ad;
    }
    __syncthreads();

    float* sattn = pool;  // overlays x (dead)
    {
        int p = tid >> 2, q = tid & 3;
        float sp = sS[p];
        float l[16]; float mx = -1e30f;
        #pragma unroll
        for (int mm = 0; mm < 16; mm++) {
            float v = sp + sD[q*16 + mm];
            v = (v > 0.f) ? v : 0.2f*v;
            l[mm] = v; mx = fmaxf(mx, v);
        }
        mx = fmaxf(mx, __shfl_xor_sync(0xffffffffu, mx, 1));
        mx = fmaxf(mx, __shfl_xor_sync(0xffffffffu, mx, 2));
        float sum = 0.f;
        #pragma unroll
        for (int mm = 0; mm < 16; mm++) {
            float e = __expf(l[mm] - mx);
            sattn[p*64 + q*16 + mm] = e; sum += e;
        }
        sum += __shfl_xor_sync(0xffffffffu, sum, 1);
        sum += __shfl_xor_sync(0xffffffffu, sum, 2);
        if (q == 0) srinv[p] = 1.0f / sum;
    }
    __syncthreads();

    for (int it = tid; it < 512; it += 256) {
        int p = it >> 3, o4 = it & 7;
        const float* ap = &sattn[p*64];
        const float4* hp4 = (const float4*)shp;
        float4 acc = {0.f,0.f,0.f,0.f};
        #pragma unroll
        for (int m = 0; m < 64; m++) fma4(acc, ap[m], hp4[m*8 + o4]);
        float ri = srinv[p];
        float4 bb = sb1v[o4];
        float4 res;
        res.x = acc.x*ri + bb.x; res.y = acc.y*ri + bb.y;
        res.z = acc.z*ri + bb.z; res.w = acc.w*ri + bb.w;
        ((float4*)g_graph_in)[((size_t)tIdx*NN + sIdx*64 + p)*8 + o4] = res;
    }
}

// ---------------------------------------------------------------------------
// LSTM graph (fused x+h): input 32, hidden 32. 4 peds/thread.
// (unchanged from R7 — measured good)
// ---------------------------------------------------------------------------
__global__ void lstm_graph_kernel(
        const float* __restrict__ h0, const float* __restrict__ c0,
        const float* __restrict__ Wih, const float* __restrict__ Whh,
        const float* __restrict__ bih, const float* __restrict__ bhh,
        float* __restrict__ hs)
{
    __shared__ __align__(16) float4 sWih4[1024];  // [k][lane] -> gates
    __shared__ __align__(16) float4 sWhh4[1024];
    __shared__ __align__(16) float4 sb4[32];
    const int tid = threadIdx.x;

    for (int i = tid; i < 4096; i += 256) {
        int r = i >> 5, k = i & 31;
        int idx = (k*32 + (r & 31))*4 + (r >> 5);
        ((float*)sWih4)[idx] = Wih[i];
        ((float*)sWhh4)[idx] = Whh[i];
    }
    if (tid < 128) ((float*)sb4)[(tid & 31)*4 + (tid >> 5)] = bih[tid] + bhh[tid];
    __syncthreads();

    const int lane = tid & 31;
    const int n0 = blockIdx.x * 32 + (tid >> 5) * 4;

    float h[4], c[4];
    #pragma unroll
    for (int r = 0; r < 4; r++) { h[r] = h0[(n0+r)*32 + lane]; c[r] = c0[(n0+r)*32 + lane]; }

    #pragma unroll 1
    for (int t = 0; t < TT; t++) {
        const float4 bb = sb4[lane];
        float xv[4];
        float4 a[4];
        #pragma unroll
        for (int r = 0; r < 4; r++) {
            xv[r] = g_graph_in[((size_t)t*NN + n0 + r)*32 + lane];
            a[r] = bb;
        }
        #pragma unroll
        for (int k = 0; k < 32; k++) {
            float4 wi = sWih4[k*32 + lane];
            float4 wh = sWhh4[k*32 + lane];
            #pragma unroll
            for (int r = 0; r < 4; r++) {
                float xk = __shfl_sync(0xffffffffu, xv[r], k);
                float hk = __shfl_sync(0xffffffffu, h[r],  k);
                fma4(a[r], xk, wi);
                fma4(a[r], hk, wh);
            }
        }
        #pragma unroll
        for (int r = 0; r < 4; r++) {
            c[r] = sig_fast(a[r].y) * c[r] + sig_fast(a[r].x) * tanh_fast(a[r].z);
            h[r] = sig_fast(a[r].w) * tanh_fast(c[r]);
            hs[((size_t)t*NN + n0 + r)*32 + lane] = h[r];
        }
    }
}

// ---------------------------------------------------------------------------
// Concat (float4): encoded[n] = [traj_hs[7,n] | graph_hs[7,n] | z[n/64]]
// ---------------------------------------------------------------------------
__global__ void concat_kernel(const float* __restrict__ z,
        const float* __restrict__ traj, const float* __restrict__ graph,
        float* __restrict__ out)
{
    int idx = blockIdx.x * blockDim.x + threadIdx.x;
    if (idx >= NN*18) return;
    int n = idx / 18, j = idx - n*18;
    float4 v;
    if (j < 8)       v = ((const float4*)traj)[((size_t)7*NN + n)*8 + j];
    else if (j < 16) v = ((const float4*)graph)[((size_t)7*NN + n)*8 + (j - 8)];
    else             v = ((const float4*)z)[(n >> 6)*2 + (j - 16)];
    ((float4*)out)[idx] = v;
}

extern "C" void kernel_launch(void* const* d_in, const int* in_sizes, int n_in,
                              void* d_out, int out_size) {
    const float* obs  = (const float*)d_in[0];
    const float* h0t  = (const float*)d_in[1];
    const float* c0t  = (const float*)d_in[2];
    const float* h0g  = (const float*)d_in[3];
    const float* c0g  = (const float*)d_in[4];
    const float* z    = (const float*)d_in[5];
    const float* WihT = (const float*)d_in[6];
    const float* WhhT = (const float*)d_in[7];
    const float* bihT = (const float*)d_in[8];
    const float* bhhT = (const float*)d_in[9];
    const float* WihG = (const float*)d_in[10];
    const float* WhhG = (const float*)d_in[11];
    const float* bihG = (const float*)d_in[12];
    const float* bhhG = (const float*)d_in[13];
    const float* w0   = (const float*)d_in[14];
    const float* as0  = (const float*)d_in[15];
    const float* ad0  = (const float*)d_in[16];
    const float* b0   = (const float*)d_in[17];
    const float* w1   = (const float*)d_in[18];
    const float* as1  = (const float*)d_in[19];
    const float* ad1  = (const float*)d_in[20];
    const float* b1   = (const float*)d_in[21];
    float* out = (float*)d_out;

    float* traj_hs;
    float* graph_hs;
    if (out_size >= ENC_ELEMS + 2*SEQ_ELEMS) {
        graph_hs = out + ENC_ELEMS;
        traj_hs  = out + ENC_ELEMS + SEQ_ELEMS;
    } else {
        void* pt = nullptr; void* pg = nullptr;
        cudaGetSymbolAddress(&pt, g_traj_fb);
        cudaGetSymbolAddress(&pg, g_graph_fb);
        traj_hs  = (float*)pt;
        graph_hs = (float*)pg;
    }

    lstm_traj_kernel<<<NN/32, 256>>>(obs, h0t, c0t, WihT, WhhT, bihT, bhhT, traj_hs);
    gat0_kernel<<<SS*TT, 256>>>(traj_hs, w0, as0, ad0, b0);
    gat1_kernel<<<SS*TT, 256>>>(w1, as1, ad1, b1);
    lstm_graph_kernel<<<NN/32, 256>>>(h0g, c0g, WihG, WhhG, bihG, bhhG, graph_hs);
    concat_kernel<<<(NN*18 + 255)/256, 256>>>(z, traj_hs, graph_hs, out);
}

// round 9
// speedup vs baseline: 2.6289x; 1.0747x over previous
#include <cuda_runtime.h>
#include <math.h>

#define SS 512
#define PP 64
#define TT 8
#define NN (SS*PP)            // 32768

#define ENC_ELEMS (NN*72)     // 2359296
#define SEQ_ELEMS (TT*NN*32)  // 8388608

#define AST 68                // padded attention row stride (floats); 68%32=4 -> conflict-free p-rows

__device__ float g_graph_in[SEQ_ELEMS];        // GAT output -> graph LSTM input
__device__ float g_x2[(size_t)SS*TT*64*64];    // GAT layer0 output (elu'd)
__device__ float g_traj_fb[SEQ_ELEMS];
__device__ float g_graph_fb[SEQ_ELEMS];

__device__ __forceinline__ float tanh_fast(float x){
    float y; asm("tanh.approx.f32 %0, %1;" : "=f"(y) : "f"(x)); return y;
}
__device__ __forceinline__ float sig_fast(float x){
    return 0.5f * tanh_fast(0.5f * x) + 0.5f;
}
__device__ __forceinline__ void fma4(float4& a, float s, const float4 w){
    a.x += s*w.x; a.y += s*w.y; a.z += s*w.z; a.w += s*w.w;
}

// ---------------------------------------------------------------------------
// LSTM traj: input 3, hidden 32, T=8. lane = hidden unit, 4 peds/thread.
// (unchanged — measured good)
// ---------------------------------------------------------------------------
__global__ void lstm_traj_kernel(const float* __restrict__ x,
        const float* __restrict__ h0, const float* __restrict__ c0,
        const float* __restrict__ Wih, const float* __restrict__ Whh,
        const float* __restrict__ bih, const float* __restrict__ bhh,
        float* __restrict__ hs)
{
    __shared__ __align__(16) float4 sWhh4[1024];  // [k][lane] -> gates
    __shared__ __align__(16) float4 sWihP[96];    // [j=0..2][lane] -> gates
    __shared__ __align__(16) float4 sb4[32];
    const int tid = threadIdx.x;

    for (int i = tid; i < 4096; i += 256) {
        int r = i >> 5, k = i & 31;   // Whh[r][k]
        ((float*)sWhh4)[(k*32 + (r & 31))*4 + (r >> 5)] = Whh[i];
    }
    for (int i = tid; i < 384; i += 256) {
        int r = i / 3, j = i - r*3;
        ((float*)sWihP)[(j*32 + (r & 31))*4 + (r >> 5)] = Wih[i];
    }
    if (tid < 128) ((float*)sb4)[(tid & 31)*4 + (tid >> 5)] = bih[tid] + bhh[tid];
    __syncthreads();

    const int lane = tid & 31;
    const int n0 = blockIdx.x * 32 + (tid >> 5) * 4;

    float h[4], c[4];
    #pragma unroll
    for (int r = 0; r < 4; r++) { h[r] = h0[(n0+r)*32 + lane]; c[r] = c0[(n0+r)*32 + lane]; }

    #pragma unroll 1
    for (int t = 0; t < TT; t++) {
        const float4 w0 = sWihP[lane], w1 = sWihP[32 + lane], w2 = sWihP[64 + lane];
        const float4 bb = sb4[lane];
        const float* xp = x + ((size_t)t*NN + n0) * 3;
        float4 a[4];
        #pragma unroll
        for (int r = 0; r < 4; r++) {
            a[r] = bb;
            fma4(a[r], xp[r*3+0], w0); fma4(a[r], xp[r*3+1], w1); fma4(a[r], xp[r*3+2], w2);
        }
        #pragma unroll
        for (int k = 0; k < 32; k++) {
            float4 w = sWhh4[k*32 + lane];
            #pragma unroll
            for (int r = 0; r < 4; r++) {
                float hk = __shfl_sync(0xffffffffu, h[r], k);
                fma4(a[r], hk, w);
            }
        }
        #pragma unroll
        for (int r = 0; r < 4; r++) {
            c[r] = sig_fast(a[r].y) * c[r] + sig_fast(a[r].x) * tanh_fast(a[r].z);
            h[r] = sig_fast(a[r].w) * tanh_fast(c[r]);
            hs[((size_t)t*NN + n0 + r)*32 + lane] = h[r];
        }
    }
}

// ---------------------------------------------------------------------------
// GAT layer 0: float4 matmuls + parallel softmax + PADDED attn (stride 68)
// ---------------------------------------------------------------------------
__global__ void gat0_kernel(const float* __restrict__ traj,
        const float* __restrict__ w0, const float* __restrict__ as0,
        const float* __restrict__ ad0, const float* __restrict__ b0)
{
    __shared__ __align__(16) float pool[4416];  // [0:2048)=x, [2048:4096)=w; later attn[64][AST]
    __shared__ __align__(16) float shp[4096];   // hp[p][h*16+o]
    __shared__ float sS[256], sD[256];
    __shared__ __align__(16) float smean[32], sinv[32];
    __shared__ float srinv[64];
    __shared__ float sas[64], sad[64];
    __shared__ __align__(16) float4 sb0v[4];

    float4* sx4 = (float4*)pool;            // 512 float4
    float4* sw4 = (float4*)(pool + 2048);   // 512 float4: w(h,f,o4) at h*128+f*4+o4
    const int tid = threadIdx.x;
    const int b = blockIdx.x, sIdx = b >> 3, tIdx = b & 7;

    {
        const float4* src = (const float4*)(traj + ((size_t)tIdx*NN + sIdx*64) * 32);
        for (int i = tid; i < 512; i += 256) sx4[i] = src[i];
        const float4* wsrc = (const float4*)w0;
        for (int i = tid; i < 512; i += 256) sw4[i] = wsrc[i];
        if (tid < 64) { sas[tid] = as0[tid]; sad[tid] = ad0[tid]; }
        if (tid < 4)  sb0v[tid] = ((const float4*)b0)[tid];
    }
    __syncthreads();

    // instance norm stats over p per feature
    if (tid < 32) {
        const float* xs = pool;
        float s = 0.f, s2 = 0.f;
        for (int p = 0; p < 64; p++) { float v = xs[p*32 + tid]; s += v; s2 += v*v; }
        float m = s * (1.0f/64.0f);
        float var = s2 * (1.0f/64.0f) - m*m;
        smean[tid] = m; sinv[tid] = rsqrtf(var + 1e-5f);
    }
    __syncthreads();
    for (int i = tid; i < 512; i += 256) {
        int f4 = i & 7;
        float4 m4 = ((float4*)smean)[f4], i4 = ((float4*)sinv)[f4];
        float4 v = sx4[i];
        v.x = (v.x - m4.x)*i4.x; v.y = (v.y - m4.y)*i4.y;
        v.z = (v.z - m4.z)*i4.z; v.w = (v.w - m4.w)*i4.w;
        sx4[i] = v;
    }
    __syncthreads();

    // hp[p][hh*16 + o4*4 + e] : 1024 quads of 4 outputs
    for (int it = tid; it < 1024; it += 256) {
        int p = it >> 4, j = it & 15, hh = j >> 2, o4 = j & 3;
        float4 acc = {0.f,0.f,0.f,0.f};
        #pragma unroll
        for (int f4 = 0; f4 < 8; f4++) {
            float4 xv = sx4[p*8 + f4];
            fma4(acc, xv.x, sw4[hh*128 + (f4*4+0)*4 + o4]);
            fma4(acc, xv.y, sw4[hh*128 + (f4*4+1)*4 + o4]);
            fma4(acc, xv.z, sw4[hh*128 + (f4*4+2)*4 + o4]);
            fma4(acc, xv.w, sw4[hh*128 + (f4*4+3)*4 + o4]);
        }
        ((float4*)shp)[p*16 + hh*4 + o4] = acc;
    }
    __syncthreads();

    // s[h][p], d[h][p]
    {
        int hh = tid >> 6, p = tid & 63;
        const float4* hp4 = (const float4*)shp;
        float as = 0.f, ad = 0.f;
        #pragma unroll
        for (int o4 = 0; o4 < 4; o4++) {
            float4 v = hp4[p*16 + hh*4 + o4];
            int ob = hh*16 + o4*4;
            as += v.x*sas[ob] + v.y*sas[ob+1] + v.z*sas[ob+2] + v.w*sas[ob+3];
            ad += v.x*sad[ob] + v.y*sad[ob+1] + v.z*sad[ob+2] + v.w*sad[ob+3];
        }
        sS[tid] = as; sD[tid] = ad;
    }
    __syncthreads();

    float* sattn = pool;  // [64][AST], overlays x+w (both dead)

    for (int hh = 0; hh < 4; hh++) {
        // softmax: 4 threads per row
        {
            int p = tid >> 2, q = tid & 3;
            float sp = sS[hh*64 + p];
            float l[16]; float mx = -1e30f;
            #pragma unroll
            for (int mm = 0; mm < 16; mm++) {
                float v = sp + sD[hh*64 + q*16 + mm];
                v = (v > 0.f) ? v : 0.2f*v;
                l[mm] = v; mx = fmaxf(mx, v);
            }
            mx = fmaxf(mx, __shfl_xor_sync(0xffffffffu, mx, 1));
            mx = fmaxf(mx, __shfl_xor_sync(0xffffffffu, mx, 2));
            float sum = 0.f;
            #pragma unroll
            for (int mm = 0; mm < 16; mm++) {
                float e = __expf(l[mm] - mx);
                sattn[p*AST + q*16 + mm] = e; sum += e;
            }
            sum += __shfl_xor_sync(0xffffffffu, sum, 1);
            sum += __shfl_xor_sync(0xffffffffu, sum, 2);
            if (q == 0) srinv[p] = 1.0f / sum;
        }
        __syncthreads();
        // apply: thread = (p, o4)
        {
            int p = tid >> 2, o4 = tid & 3;
            const float* ap = &sattn[p*AST];
            const float4* hp4 = (const float4*)shp;
            float4 acc = {0.f,0.f,0.f,0.f};
            #pragma unroll
            for (int m = 0; m < 64; m++) fma4(acc, ap[m], hp4[m*16 + hh*4 + o4]);
            float ri = srinv[p];
            float4 bb = sb0v[o4];
            float4 res;
            res.x = acc.x*ri + bb.x; res.y = acc.y*ri + bb.y;
            res.z = acc.z*ri + bb.z; res.w = acc.w*ri + bb.w;
            res.x = (res.x > 0.f) ? res.x : (__expf(res.x) - 1.f);
            res.y = (res.y > 0.f) ? res.y : (__expf(res.y) - 1.f);
            res.z = (res.z > 0.f) ? res.z : (__expf(res.z) - 1.f);
            res.w = (res.w > 0.f) ? res.w : (__expf(res.w) - 1.f);
            ((float4*)g_x2)[((size_t)b*64 + p)*16 + hh*4 + o4] = res;
        }
        __syncthreads();
    }
}

// ---------------------------------------------------------------------------
// GAT layer 1: float4 matmuls + parallel softmax + PADDED attn (stride 68)
// ---------------------------------------------------------------------------
__global__ void gat1_kernel(const float* __restrict__ w1, const float* __restrict__ as1,
        const float* __restrict__ ad1, const float* __restrict__ b1)
{
    __shared__ __align__(16) float pool[4416];  // sx / sattn (padded)
    __shared__ __align__(16) float sw[2048];    // w(f,o4) at f*8+o4 (float4)
    __shared__ __align__(16) float shp[2048];
    __shared__ float sS[64], sD[64];
    __shared__ __align__(16) float smean[64], sinv[64];
    __shared__ float srinv[64], sas[32], sad[32];
    __shared__ __align__(16) float4 sb1v[8];

    float4* sx4 = (float4*)pool;          // 1024 float4
    float4* sw4 = (float4*)sw;            // 512 float4
    const int tid = threadIdx.x;
    const int b = blockIdx.x, sIdx = b >> 3, tIdx = b & 7;

    {
        const float4* src = (const float4*)(g_x2 + (size_t)b*4096);
        for (int i = tid; i < 1024; i += 256) sx4[i] = src[i];
        const float4* wsrc = (const float4*)w1;
        for (int i = tid; i < 512; i += 256) sw4[i] = wsrc[i];
        if (tid < 32) { sas[tid] = as1[tid]; sad[tid] = ad1[tid]; }
        if (tid < 8)  sb1v[tid] = ((const float4*)b1)[tid];
    }
    __syncthreads();

    if (tid < 64) {
        float s = 0.f, s2 = 0.f;
        for (int p = 0; p < 64; p++) { float v = pool[p*64 + tid]; s += v; s2 += v*v; }
        float m = s * (1.0f/64.0f);
        float var = s2 * (1.0f/64.0f) - m*m;
        smean[tid] = m; sinv[tid] = rsqrtf(var + 1e-5f);
    }
    __syncthreads();
    for (int i = tid; i < 1024; i += 256) {
        int f4 = i & 15;
        float4 m4 = ((float4*)smean)[f4], i4 = ((float4*)sinv)[f4];
        float4 v = sx4[i];
        v.x = (v.x - m4.x)*i4.x; v.y = (v.y - m4.y)*i4.y;
        v.z = (v.z - m4.z)*i4.z; v.w = (v.w - m4.w)*i4.w;
        sx4[i] = v;
    }
    __syncthreads();

    // hp: 512 quads (p, o4), 2 per thread
    for (int it = tid; it < 512; it += 256) {
        int p = it >> 3, o4 = it & 7;
        float4 acc = {0.f,0.f,0.f,0.f};
        #pragma unroll
        for (int f4 = 0; f4 < 16; f4++) {
            float4 xv = sx4[p*16 + f4];
            fma4(acc, xv.x, sw4[(f4*4+0)*8 + o4]);
            fma4(acc, xv.y, sw4[(f4*4+1)*8 + o4]);
            fma4(acc, xv.z, sw4[(f4*4+2)*8 + o4]);
            fma4(acc, xv.w, sw4[(f4*4+3)*8 + o4]);
        }
        ((float4*)shp)[p*8 + o4] = acc;
    }
    __syncthreads();

    if (tid < 64) {
        int p = tid;
        const float4* hp4 = (const float4*)shp;
        float as = 0.f, ad = 0.f;
        #pragma unroll
        for (int o4 = 0; o4 < 8; o4++) {
            float4 v = hp4[p*8 + o4];
            as += v.x*sas[o4*4] + v.y*sas[o4*4+1] + v.z*sas[o4*4+2] + v.w*sas[o4*4+3];
            ad += v.x*sad[o4*4] + v.y*sad[o4*4+1] + v.z*sad[o4*4+2] + v.w*sad[o4*4+3];
        }
        sS[p] = as; sD[p] = ad;
    }
    __syncthreads();

    float* sattn = pool;  // overlays x (dead), stride AST
    {
        int p = tid >> 2, q = tid & 3;
        float sp = sS[p];
        float l[16]; float mx = -1e30f;
        #pragma unroll
        for (int mm = 0; mm < 16; mm++) {
            float v = sp + sD[q*16 + mm];
            v = (v > 0.f) ? v : 0.2f*v;
            l[mm] = v; mx = fmaxf(mx, v);
        }
        mx = fmaxf(mx, __shfl_xor_sync(0xffffffffu, mx, 1));
        mx = fmaxf(mx, __shfl_xor_sync(0xffffffffu, mx, 2));
        float sum = 0.f;
        #pragma unroll
        for (int mm = 0; mm < 16; mm++) {
            float e = __expf(l[mm] - mx);
            sattn[p*AST + q*16 + mm] = e; sum += e;
        }
        sum += __shfl_xor_sync(0xffffffffu, sum, 1);
        sum += __shfl_xor_sync(0xffffffffu, sum, 2);
        if (q == 0) srinv[p] = 1.0f / sum;
    }
    __syncthreads();

    for (int it = tid; it < 512; it += 256) {
        int p = it >> 3, o4 = it & 7;
        const float* ap = &sattn[p*AST];
        const float4* hp4 = (const float4*)shp;
        float4 acc = {0.f,0.f,0.f,0.f};
        #pragma unroll
        for (int m = 0; m < 64; m++) fma4(acc, ap[m], hp4[m*8 + o4]);
        float ri = srinv[p];
        float4 bb = sb1v[o4];
        float4 res;
        res.x = acc.x*ri + bb.x; res.y = acc.y*ri + bb.y;
        res.z = acc.z*ri + bb.z; res.w = acc.w*ri + bb.w;
        ((float4*)g_graph_in)[((size_t)tIdx*NN + sIdx*64 + p)*8 + o4] = res;
    }
}

// ---------------------------------------------------------------------------
// LSTM graph (fused x+h): input 32, hidden 32. 4 peds/thread.
// (unchanged — measured good)
// ---------------------------------------------------------------------------
__global__ void lstm_graph_kernel(
        const float* __restrict__ h0, const float* __restrict__ c0,
        const float* __restrict__ Wih, const float* __restrict__ Whh,
        const float* __restrict__ bih, const float* __restrict__ bhh,
        float* __restrict__ hs)
{
    __shared__ __align__(16) float4 sWih4[1024];  // [k][lane] -> gates
    __shared__ __align__(16) float4 sWhh4[1024];
    __shared__ __align__(16) float4 sb4[32];
    const int tid = threadIdx.x;

    for (int i = tid; i < 4096; i += 256) {
        int r = i >> 5, k = i & 31;
        int idx = (k*32 + (r & 31))*4 + (r >> 5);
        ((float*)sWih4)[idx] = Wih[i];
        ((float*)sWhh4)[idx] = Whh[i];
    }
    if (tid < 128) ((float*)sb4)[(tid & 31)*4 + (tid >> 5)] = bih[tid] + bhh[tid];
    __syncthreads();

    const int lane = tid & 31;
    const int n0 = blockIdx.x * 32 + (tid >> 5) * 4;

    float h[4], c[4];
    #pragma unroll
    for (int r = 0; r < 4; r++) { h[r] = h0[(n0+r)*32 + lane]; c[r] = c0[(n0+r)*32 + lane]; }

    #pragma unroll 1
    for (int t = 0; t < TT; t++) {
        const float4 bb = sb4[lane];
        float xv[4];
        float4 a[4];
        #pragma unroll
        for (int r = 0; r < 4; r++) {
            xv[r] = g_graph_in[((size_t)t*NN + n0 + r)*32 + lane];
            a[r] = bb;
        }
        #pragma unroll
        for (int k = 0; k < 32; k++) {
            float4 wi = sWih4[k*32 + lane];
            float4 wh = sWhh4[k*32 + lane];
            #pragma unroll
            for (int r = 0; r < 4; r++) {
                float xk = __shfl_sync(0xffffffffu, xv[r], k);
                float hk = __shfl_sync(0xffffffffu, h[r],  k);
                fma4(a[r], xk, wi);
                fma4(a[r], hk, wh);
            }
        }
        #pragma unroll
        for (int r = 0; r < 4; r++) {
            c[r] = sig_fast(a[r].y) * c[r] + sig_fast(a[r].x) * tanh_fast(a[r].z);
            h[r] = sig_fast(a[r].w) * tanh_fast(c[r]);
            hs[((size_t)t*NN + n0 + r)*32 + lane] = h[r];
        }
    }
}

// ---------------------------------------------------------------------------
// Concat (float4): encoded[n] = [traj_hs[7,n] | graph_hs[7,n] | z[n/64]]
// ---------------------------------------------------------------------------
__global__ void concat_kernel(const float* __restrict__ z,
        const float* __restrict__ traj, const float* __restrict__ graph,
        float* __restrict__ out)
{
    int idx = blockIdx.x * blockDim.x + threadIdx.x;
    if (idx >= NN*18) return;
    int n = idx / 18, j = idx - n*18;
    float4 v;
    if (j < 8)       v = ((const float4*)traj)[((size_t)7*NN + n)*8 + j];
    else if (j < 16) v = ((const float4*)graph)[((size_t)7*NN + n)*8 + (j - 8)];
    else             v = ((const float4*)z)[(n >> 6)*2 + (j - 16)];
    ((float4*)out)[idx] = v;
}

extern "C" void kernel_launch(void* const* d_in, const int* in_sizes, int n_in,
                              void* d_out, int out_size) {
    const float* obs  = (const float*)d_in[0];
    const float* h0t  = (const float*)d_in[1];
    const float* c0t  = (const float*)d_in[2];
    const float* h0g  = (const float*)d_in[3];
    const float* c0g  = (const float*)d_in[4];
    const float* z    = (const float*)d_in[5];
    const float* WihT = (const float*)d_in[6];
    const float* WhhT = (const float*)d_in[7];
    const float* bihT = (const float*)d_in[8];
    const float* bhhT = (const float*)d_in[9];
    const float* WihG = (const float*)d_in[10];
    const float* WhhG = (const float*)d_in[11];
    const float* bihG = (const float*)d_in[12];
    const float* bhhG = (const float*)d_in[13];
    const float* w0   = (const float*)d_in[14];
    const float* as0  = (const float*)d_in[15];
    const float* ad0  = (const float*)d_in[16];
    const float* b0   = (const float*)d_in[17];
    const float* w1   = (const float*)d_in[18];
    const float* as1  = (const float*)d_in[19];
    const float* ad1  = (const float*)d_in[20];
    const float* b1   = (const float*)d_in[21];
    float* out = (float*)d_out;

    float* traj_hs;
    float* graph_hs;
    if (out_size >= ENC_ELEMS + 2*SEQ_ELEMS) {
        graph_hs = out + ENC_ELEMS;
        traj_hs  = out + ENC_ELEMS + SEQ_ELEMS;
    } else {
        void* pt = nullptr; void* pg = nullptr;
        cudaGetSymbolAddress(&pt, g_traj_fb);
        cudaGetSymbolAddress(&pg, g_graph_fb);
        traj_hs  = (float*)pt;
        graph_hs = (float*)pg;
    }

    lstm_traj_kernel<<<NN/32, 256>>>(obs, h0t, c0t, WihT, WhhT, bihT, bhhT, traj_hs);
    gat0_kernel<<<SS*TT, 256>>>(traj_hs, w0, as0, ad0, b0);
    gat1_kernel<<<SS*TT, 256>>>(w1, as1, ad1, b1);
    lstm_graph_kernel<<<NN/32, 256>>>(h0g, c0g, WihG, WhhG, bihG, bhhG, graph_hs);
    concat_kernel<<<(NN*18 + 255)/256, 256>>>(z, traj_hs, graph_hs, out);
}

// round 10
// speedup vs baseline: 2.7792x; 1.0572x over previous
#include <cuda_runtime.h>
#include <math.h>

#define SS 512
#define PP 64
#define TT 8
#define NN (SS*PP)            // 32768

#define ENC_ELEMS (NN*72)     // 2359296
#define SEQ_ELEMS (TT*NN*32)  // 8388608

#define AST 68                // padded attention row stride (floats)

typedef unsigned long long u64;

__device__ float g_graph_in[SEQ_ELEMS];        // GAT output -> graph LSTM input
__device__ float g_x2[(size_t)SS*TT*64*64];    // GAT layer0 output (elu'd)
__device__ float g_traj_fb[SEQ_ELEMS];
__device__ float g_graph_fb[SEQ_ELEMS];

__device__ __forceinline__ float tanh_fast(float x){
    float y; asm("tanh.approx.f32 %0, %1;" : "=f"(y) : "f"(x)); return y;
}
__device__ __forceinline__ float sig_fast(float x){
    return 0.5f * tanh_fast(0.5f * x) + 0.5f;
}
__device__ __forceinline__ void fma4(float4& a, float s, const float4 w){
    a.x += s*w.x; a.y += s*w.y; a.z += s*w.z; a.w += s*w.w;
}

#define FMA2(d, a, b) asm("fma.rn.f32x2 %0, %1, %2, %0;" : "+l"(d) : "l"(a), "l"(b))
#define PACK2(d, lo, hi) asm("mov.b64 %0, {%1, %2};" : "=l"(d) : "f"(lo), "f"(hi))
#define UNPACK2(lo, hi, s) asm("mov.b64 {%0, %1}, %2;" : "=f"(lo), "=f"(hi) : "l"(s))

// ---------------------------------------------------------------------------
// LSTM traj: input 3, hidden 32, T=8. Warp = 4 peds, lane = hidden unit.
// Packed f32x2 accumulators over ped pairs; h broadcast via interleaved smem.
// ---------------------------------------------------------------------------
__global__ void lstm_traj_kernel(const float* __restrict__ x,
        const float* __restrict__ h0, const float* __restrict__ c0,
        const float* __restrict__ Wih, const float* __restrict__ Whh,
        const float* __restrict__ bih, const float* __restrict__ bhh,
        float* __restrict__ hs)
{
    __shared__ __align__(16) float4 sWhh4[1024];  // [k][lane] -> gates
    __shared__ __align__(16) float4 sWihP[96];    // [j=0..2][lane] -> gates
    __shared__ __align__(16) float4 sb4[32];
    __shared__ __align__(8)  float shhf[1024];    // [w][pp][k][c] pair-interleaved
    const int tid = threadIdx.x;

    for (int i = tid; i < 4096; i += 256) {
        int r = i >> 5, k = i & 31;
        ((float*)sWhh4)[(k*32 + (r & 31))*4 + (r >> 5)] = Whh[i];
    }
    for (int i = tid; i < 384; i += 256) {
        int r = i / 3, j = i - r*3;
        ((float*)sWihP)[(j*32 + (r & 31))*4 + (r >> 5)] = Wih[i];
    }
    if (tid < 128) ((float*)sb4)[(tid & 31)*4 + (tid >> 5)] = bih[tid] + bhh[tid];
    __syncthreads();

    const int lane = tid & 31;
    const int w2 = (tid >> 5) * 2;
    const int n0 = blockIdx.x * 32 + w2 * 2;

    float h[4], c[4];
    #pragma unroll
    for (int r = 0; r < 4; r++) { h[r] = h0[(n0+r)*32 + lane]; c[r] = c0[(n0+r)*32 + lane]; }

    const float4 bb = sb4[lane];
    u64 bd[4];
    PACK2(bd[0], bb.x, bb.x); PACK2(bd[1], bb.y, bb.y);
    PACK2(bd[2], bb.z, bb.z); PACK2(bd[3], bb.w, bb.w);

    const u64* hp0 = (const u64*)shhf + (w2 + 0)*32;
    const u64* hp1 = (const u64*)shhf + (w2 + 1)*32;

    #pragma unroll 1
    for (int t = 0; t < TT; t++) {
        __syncwarp();
        #pragma unroll
        for (int r = 0; r < 4; r++)
            shhf[((w2 + (r>>1))*32 + lane)*2 + (r&1)] = h[r];
        __syncwarp();

        u64 ac[8];   // [g*2 + pp]
        #pragma unroll
        for (int g = 0; g < 4; g++) { ac[g*2] = bd[g]; ac[g*2+1] = bd[g]; }

        // x part: 3 inputs
        const float* xp = x + ((size_t)t*NN + n0) * 3;
        #pragma unroll
        for (int j = 0; j < 3; j++) {
            float4 wj = sWihP[j*32 + lane];
            u64 xq0, xq1, d0, d1, d2, d3;
            PACK2(xq0, xp[0*3+j], xp[1*3+j]);
            PACK2(xq1, xp[2*3+j], xp[3*3+j]);
            PACK2(d0, wj.x, wj.x); PACK2(d1, wj.y, wj.y);
            PACK2(d2, wj.z, wj.z); PACK2(d3, wj.w, wj.w);
            FMA2(ac[0], xq0, d0); FMA2(ac[1], xq1, d0);
            FMA2(ac[2], xq0, d1); FMA2(ac[3], xq1, d1);
            FMA2(ac[4], xq0, d2); FMA2(ac[5], xq1, d2);
            FMA2(ac[6], xq0, d3); FMA2(ac[7], xq1, d3);
        }

        // h recurrence
        #pragma unroll
        for (int k = 0; k < 32; k++) {
            float4 wh = sWhh4[k*32 + lane];
            u64 hq0 = hp0[k], hq1 = hp1[k];
            u64 d0, d1, d2, d3;
            PACK2(d0, wh.x, wh.x); PACK2(d1, wh.y, wh.y);
            PACK2(d2, wh.z, wh.z); PACK2(d3, wh.w, wh.w);
            FMA2(ac[0], hq0, d0); FMA2(ac[1], hq1, d0);
            FMA2(ac[2], hq0, d1); FMA2(ac[3], hq1, d1);
            FMA2(ac[4], hq0, d2); FMA2(ac[5], hq1, d2);
            FMA2(ac[6], hq0, d3); FMA2(ac[7], hq1, d3);
        }

        float A[4][4];
        #pragma unroll
        for (int g = 0; g < 4; g++) {
            UNPACK2(A[g][0], A[g][1], ac[g*2]);
            UNPACK2(A[g][2], A[g][3], ac[g*2+1]);
        }
        #pragma unroll
        for (int r = 0; r < 4; r++) {
            c[r] = sig_fast(A[1][r]) * c[r] + sig_fast(A[0][r]) * tanh_fast(A[2][r]);
            h[r] = sig_fast(A[3][r]) * tanh_fast(c[r]);
            hs[((size_t)t*NN + n0 + r)*32 + lane] = h[r];
        }
    }
}

// ---------------------------------------------------------------------------
// GAT layer 0 (unchanged from R9 — padded attn)
// ---------------------------------------------------------------------------
__global__ void gat0_kernel(const float* __restrict__ traj,
        const float* __restrict__ w0, const float* __restrict__ as0,
        const float* __restrict__ ad0, const float* __restrict__ b0)
{
    __shared__ __align__(16) float pool[4416];
    __shared__ __align__(16) float shp[4096];
    __shared__ float sS[256], sD[256];
    __shared__ __align__(16) float smean[32], sinv[32];
    __shared__ float srinv[64];
    __shared__ float sas[64], sad[64];
    __shared__ __align__(16) float4 sb0v[4];

    float4* sx4 = (float4*)pool;
    float4* sw4 = (float4*)(pool + 2048);
    const int tid = threadIdx.x;
    const int b = blockIdx.x, sIdx = b >> 3, tIdx = b & 7;

    {
        const float4* src = (const float4*)(traj + ((size_t)tIdx*NN + sIdx*64) * 32);
        for (int i = tid; i < 512; i += 256) sx4[i] = src[i];
        const float4* wsrc = (const float4*)w0;
        for (int i = tid; i < 512; i += 256) sw4[i] = wsrc[i];
        if (tid < 64) { sas[tid] = as0[tid]; sad[tid] = ad0[tid]; }
        if (tid < 4)  sb0v[tid] = ((const float4*)b0)[tid];
    }
    __syncthreads();

    if (tid < 32) {
        const float* xs = pool;
        float s = 0.f, s2 = 0.f;
        for (int p = 0; p < 64; p++) { float v = xs[p*32 + tid]; s += v; s2 += v*v; }
        float m = s * (1.0f/64.0f);
        float var = s2 * (1.0f/64.0f) - m*m;
        smean[tid] = m; sinv[tid] = rsqrtf(var + 1e-5f);
    }
    __syncthreads();
    for (int i = tid; i < 512; i += 256) {
        int f4 = i & 7;
        float4 m4 = ((float4*)smean)[f4], i4 = ((float4*)sinv)[f4];
        float4 v = sx4[i];
        v.x = (v.x - m4.x)*i4.x; v.y = (v.y - m4.y)*i4.y;
        v.z = (v.z - m4.z)*i4.z; v.w = (v.w - m4.w)*i4.w;
        sx4[i] = v;
    }
    __syncthreads();

    for (int it = tid; it < 1024; it += 256) {
        int p = it >> 4, j = it & 15, hh = j >> 2, o4 = j & 3;
        float4 acc = {0.f,0.f,0.f,0.f};
        #pragma unroll
        for (int f4 = 0; f4 < 8; f4++) {
            float4 xv = sx4[p*8 + f4];
            fma4(acc, xv.x, sw4[hh*128 + (f4*4+0)*4 + o4]);
            fma4(acc, xv.y, sw4[hh*128 + (f4*4+1)*4 + o4]);
            fma4(acc, xv.z, sw4[hh*128 + (f4*4+2)*4 + o4]);
            fma4(acc, xv.w, sw4[hh*128 + (f4*4+3)*4 + o4]);
        }
        ((float4*)shp)[p*16 + hh*4 + o4] = acc;
    }
    __syncthreads();

    {
        int hh = tid >> 6, p = tid & 63;
        const float4* hp4 = (const float4*)shp;
        float as = 0.f, ad = 0.f;
        #pragma unroll
        for (int o4 = 0; o4 < 4; o4++) {
            float4 v = hp4[p*16 + hh*4 + o4];
            int ob = hh*16 + o4*4;
            as += v.x*sas[ob] + v.y*sas[ob+1] + v.z*sas[ob+2] + v.w*sas[ob+3];
            ad += v.x*sad[ob] + v.y*sad[ob+1] + v.z*sad[ob+2] + v.w*sad[ob+3];
        }
        sS[tid] = as; sD[tid] = ad;
    }
    __syncthreads();

    float* sattn = pool;

    for (int hh = 0; hh < 4; hh++) {
        {
            int p = tid >> 2, q = tid & 3;
            float sp = sS[hh*64 + p];
            float l[16]; float mx = -1e30f;
            #pragma unroll
            for (int mm = 0; mm < 16; mm++) {
                float v = sp + sD[hh*64 + q*16 + mm];
                v = (v > 0.f) ? v : 0.2f*v;
                l[mm] = v; mx = fmaxf(mx, v);
            }
            mx = fmaxf(mx, __shfl_xor_sync(0xffffffffu, mx, 1));
            mx = fmaxf(mx, __shfl_xor_sync(0xffffffffu, mx, 2));
            float sum = 0.f;
            #pragma unroll
            for (int mm = 0; mm < 16; mm++) {
                float e = __expf(l[mm] - mx);
                sattn[p*AST + q*16 + mm] = e; sum += e;
            }
            sum += __shfl_xor_sync(0xffffffffu, sum, 1);
            sum += __shfl_xor_sync(0xffffffffu, sum, 2);
            if (q == 0) srinv[p] = 1.0f / sum;
        }
        __syncthreads();
        {
            int p = tid >> 2, o4 = tid & 3;
            const float* ap = &sattn[p*AST];
            const float4* hp4 = (const float4*)shp;
            float4 acc = {0.f,0.f,0.f,0.f};
            #pragma unroll
            for (int m = 0; m < 64; m++) fma4(acc, ap[m], hp4[m*16 + hh*4 + o4]);
            float ri = srinv[p];
            float4 bb = sb0v[o4];
            float4 res;
            res.x = acc.x*ri + bb.x; res.y = acc.y*ri + bb.y;
            res.z = acc.z*ri + bb.z; res.w = acc.w*ri + bb.w;
            res.x = (res.x > 0.f) ? res.x : (__expf(res.x) - 1.f);
            res.y = (res.y > 0.f) ? res.y : (__expf(res.y) - 1.f);
            res.z = (res.z > 0.f) ? res.z : (__expf(res.z) - 1.f);
            res.w = (res.w > 0.f) ? res.w : (__expf(res.w) - 1.f);
            ((float4*)g_x2)[((size_t)b*64 + p)*16 + hh*4 + o4] = res;
        }
        __syncthreads();
    }
}

// ---------------------------------------------------------------------------
// GAT layer 1 (unchanged from R9 — padded attn)
// ---------------------------------------------------------------------------
__global__ void gat1_kernel(const float* __restrict__ w1, const float* __restrict__ as1,
        const float* __restrict__ ad1, const float* __restrict__ b1)
{
    __shared__ __align__(16) float pool[4416];
    __shared__ __align__(16) float sw[2048];
    __shared__ __align__(16) float shp[2048];
    __shared__ float sS[64], sD[64];
    __shared__ __align__(16) float smean[64], sinv[64];
    __shared__ float srinv[64], sas[32], sad[32];
    __shared__ __align__(16) float4 sb1v[8];

    float4* sx4 = (float4*)pool;
    float4* sw4 = (float4*)sw;
    const int tid = threadIdx.x;
    const int b = blockIdx.x, sIdx = b >> 3, tIdx = b & 7;

    {
        const float4* src = (const float4*)(g_x2 + (size_t)b*4096);
        for (int i = tid; i < 1024; i += 256) sx4[i] = src[i];
        const float4* wsrc = (const float4*)w1;
        for (int i = tid; i < 512; i += 256) sw4[i] = wsrc[i];
        if (tid < 32) { sas[tid] = as1[tid]; sad[tid] = ad1[tid]; }
        if (tid < 8)  sb1v[tid] = ((const float4*)b1)[tid];
    }
    __syncthreads();

    if (tid < 64) {
        float s = 0.f, s2 = 0.f;
        for (int p = 0; p < 64; p++) { float v = pool[p*64 + tid]; s += v; s2 += v*v; }
        float m = s * (1.0f/64.0f);
        float var = s2 * (1.0f/64.0f) - m*m;
        smean[tid] = m; sinv[tid] = rsqrtf(var + 1e-5f);
    }
    __syncthreads();
    for (int i = tid; i < 1024; i += 256) {
        int f4 = i & 15;
        float4 m4 = ((float4*)smean)[f4], i4 = ((float4*)sinv)[f4];
        float4 v = sx4[i];
        v.x = (v.x - m4.x)*i4.x; v.y = (v.y - m4.y)*i4.y;
        v.z = (v.z - m4.z)*i4.z; v.w = (v.w - m4.w)*i4.w;
        sx4[i] = v;
    }
    __syncthreads();

    for (int it = tid; it < 512; it += 256) {
        int p = it >> 3, o4 = it & 7;
        float4 acc = {0.f,0.f,0.f,0.f};
        #pragma unroll
        for (int f4 = 0; f4 < 16; f4++) {
            float4 xv = sx4[p*16 + f4];
            fma4(acc, xv.x, sw4[(f4*4+0)*8 + o4]);
            fma4(acc, xv.y, sw4[(f4*4+1)*8 + o4]);
            fma4(acc, xv.z, sw4[(f4*4+2)*8 + o4]);
            fma4(acc, xv.w, sw4[(f4*4+3)*8 + o4]);
        }
        ((float4*)shp)[p*8 + o4] = acc;
    }
    __syncthreads();

    if (tid < 64) {
        int p = tid;
        const float4* hp4 = (const float4*)shp;
        float as = 0.f, ad = 0.f;
        #pragma unroll
        for (int o4 = 0; o4 < 8; o4++) {
            float4 v = hp4[p*8 + o4];
            as += v.x*sas[o4*4] + v.y*sas[o4*4+1] + v.z*sas[o4*4+2] + v.w*sas[o4*4+3];
            ad += v.x*sad[o4*4] + v.y*sad[o4*4+1] + v.z*sad[o4*4+2] + v.w*sad[o4*4+3];
        }
        sS[p] = as; sD[p] = ad;
    }
    __syncthreads();

    float* sattn = pool;
    {
        int p = tid >> 2, q = tid & 3;
        float sp = sS[p];
        float l[16]; float mx = -1e30f;
        #pragma unroll
        for (int mm = 0; mm < 16; mm++) {
            float v = sp + sD[q*16 + mm];
            v = (v > 0.f) ? v : 0.2f*v;
            l[mm] = v; mx = fmaxf(mx, v);
        }
        mx = fmaxf(mx, __shfl_xor_sync(0xffffffffu, mx, 1));
        mx = fmaxf(mx, __shfl_xor_sync(0xffffffffu, mx, 2));
        float sum = 0.f;
        #pragma unroll
        for (int mm = 0; mm < 16; mm++) {
            float e = __expf(l[mm] - mx);
            sattn[p*AST + q*16 + mm] = e; sum += e;
        }
        sum += __shfl_xor_sync(0xffffffffu, sum, 1);
        sum += __shfl_xor_sync(0xffffffffu, sum, 2);
        if (q == 0) srinv[p] = 1.0f / sum;
    }
    __syncthreads();

    for (int it = tid; it < 512; it += 256) {
        int p = it >> 3, o4 = it & 7;
        const float* ap = &sattn[p*AST];
        const float4* hp4 = (const float4*)shp;
        float4 acc = {0.f,0.f,0.f,0.f};
        #pragma unroll
        for (int m = 0; m < 64; m++) fma4(acc, ap[m], hp4[m*8 + o4]);
        float ri = srinv[p];
        float4 bb = sb1v[o4];
        float4 res;
        res.x = acc.x*ri + bb.x; res.y = acc.y*ri + bb.y;
        res.z = acc.z*ri + bb.z; res.w = acc.w*ri + bb.w;
        ((float4*)g_graph_in)[((size_t)tIdx*NN + sIdx*64 + p)*8 + o4] = res;
    }
}

// ---------------------------------------------------------------------------
// LSTM graph (fused x+h): input 32, hidden 32. Warp = 4 peds.
// Packed f32x2 accumulators; x/h broadcast via interleaved smem (no shuffles).
// ---------------------------------------------------------------------------
__global__ void lstm_graph_kernel(
        const float* __restrict__ h0, const float* __restrict__ c0,
        const float* __restrict__ Wih, const float* __restrict__ Whh,
        const float* __restrict__ bih, const float* __restrict__ bhh,
        float* __restrict__ hs)
{
    __shared__ __align__(16) float4 sWih4[1024];  // [k][lane] -> gates
    __shared__ __align__(16) float4 sWhh4[1024];
    __shared__ __align__(16) float4 sb4[32];
    __shared__ __align__(8)  float shxf[1024];    // [w][pp][k][c] pair-interleaved
    __shared__ __align__(8)  float shhf[1024];
    const int tid = threadIdx.x;

    for (int i = tid; i < 4096; i += 256) {
        int r = i >> 5, k = i & 31;
        int idx = (k*32 + (r & 31))*4 + (r >> 5);
        ((float*)sWih4)[idx] = Wih[i];
        ((float*)sWhh4)[idx] = Whh[i];
    }
    if (tid < 128) ((float*)sb4)[(tid & 31)*4 + (tid >> 5)] = bih[tid] + bhh[tid];
    __syncthreads();

    const int lane = tid & 31;
    const int w2 = (tid >> 5) * 2;
    const int n0 = blockIdx.x * 32 + w2 * 2;

    float h[4], c[4];
    #pragma unroll
    for (int r = 0; r < 4; r++) { h[r] = h0[(n0+r)*32 + lane]; c[r] = c0[(n0+r)*32 + lane]; }

    const float4 bb = sb4[lane];
    u64 bd[4];
    PACK2(bd[0], bb.x, bb.x); PACK2(bd[1], bb.y, bb.y);
    PACK2(bd[2], bb.z, bb.z); PACK2(bd[3], bb.w, bb.w);

    const u64* xp0 = (const u64*)shxf + (w2 + 0)*32;
    const u64* xp1 = (const u64*)shxf + (w2 + 1)*32;
    const u64* hp0 = (const u64*)shhf + (w2 + 0)*32;
    const u64* hp1 = (const u64*)shhf + (w2 + 1)*32;

    #pragma unroll 1
    for (int t = 0; t < TT; t++) {
        __syncwarp();
        #pragma unroll
        for (int r = 0; r < 4; r++) {
            int idx = ((w2 + (r>>1))*32 + lane)*2 + (r&1);
            shxf[idx] = g_graph_in[((size_t)t*NN + n0 + r)*32 + lane];
            shhf[idx] = h[r];
        }
        __syncwarp();

        u64 ac[8];   // [g*2 + pp]
        #pragma unroll
        for (int g = 0; g < 4; g++) { ac[g*2] = bd[g]; ac[g*2+1] = bd[g]; }

        #pragma unroll
        for (int k = 0; k < 32; k++) {
            float4 wi = sWih4[k*32 + lane];
            float4 wh = sWhh4[k*32 + lane];
            u64 xq0 = xp0[k], xq1 = xp1[k];
            u64 hq0 = hp0[k], hq1 = hp1[k];
            u64 d0, d1, d2, d3;
            PACK2(d0, wi.x, wi.x); PACK2(d1, wi.y, wi.y);
            PACK2(d2, wi.z, wi.z); PACK2(d3, wi.w, wi.w);
            FMA2(ac[0], xq0, d0); FMA2(ac[1], xq1, d0);
            FMA2(ac[2], xq0, d1); FMA2(ac[3], xq1, d1);
            FMA2(ac[4], xq0, d2); FMA2(ac[5], xq1, d2);
            FMA2(ac[6], xq0, d3); FMA2(ac[7], xq1, d3);
            PACK2(d0, wh.x, wh.x); PACK2(d1, wh.y, wh.y);
            PACK2(d2, wh.z, wh.z); PACK2(d3, wh.w, wh.w);
            FMA2(ac[0], hq0, d0); FMA2(ac[1], hq1, d0);
            FMA2(ac[2], hq0, d1); FMA2(ac[3], hq1, d1);
            FMA2(ac[4], hq0, d2); FMA2(ac[5], hq1, d2);
            FMA2(ac[6], hq0, d3); FMA2(ac[7], hq1, d3);
        }

        float A[4][4];
        #pragma unroll
        for (int g = 0; g < 4; g++) {
            UNPACK2(A[g][0], A[g][1], ac[g*2]);
            UNPACK2(A[g][2], A[g][3], ac[g*2+1]);
        }
        #pragma unroll
        for (int r = 0; r < 4; r++) {
            c[r] = sig_fast(A[1][r]) * c[r] + sig_fast(A[0][r]) * tanh_fast(A[2][r]);
            h[r] = sig_fast(A[3][r]) * tanh_fast(c[r]);
            hs[((size_t)t*NN + n0 + r)*32 + lane] = h[r];
        }
    }
}

// ---------------------------------------------------------------------------
// Concat (float4): encoded[n] = [traj_hs[7,n] | graph_hs[7,n] | z[n/64]]
// ---------------------------------------------------------------------------
__global__ void concat_kernel(const float* __restrict__ z,
        const float* __restrict__ traj, const float* __restrict__ graph,
        float* __restrict__ out)
{
    int idx = blockIdx.x * blockDim.x + threadIdx.x;
    if (idx >= NN*18) return;
    int n = idx / 18, j = idx - n*18;
    float4 v;
    if (j < 8)       v = ((const float4*)traj)[((size_t)7*NN + n)*8 + j];
    else if (j < 16) v = ((const float4*)graph)[((size_t)7*NN + n)*8 + (j - 8)];
    else             v = ((const float4*)z)[(n >> 6)*2 + (j - 16)];
    ((float4*)out)[idx] = v;
}

extern "C" void kernel_launch(void* const* d_in, const int* in_sizes, int n_in,
                              void* d_out, int out_size) {
    const float* obs  = (const float*)d_in[0];
    const float* h0t  = (const float*)d_in[1];
    const float* c0t  = (const float*)d_in[2];
    const float* h0g  = (const float*)d_in[3];
    const float* c0g  = (const float*)d_in[4];
    const float* z    = (const float*)d_in[5];
    const float* WihT = (const float*)d_in[6];
    const float* WhhT = (const float*)d_in[7];
    const float* bihT = (const float*)d_in[8];
    const float* bhhT = (const float*)d_in[9];
    const float* WihG = (const float*)d_in[10];
    const float* WhhG = (const float*)d_in[11];
    const float* bihG = (const float*)d_in[12];
    const float* bhhG = (const float*)d_in[13];
    const float* w0   = (const float*)d_in[14];
    const float* as0  = (const float*)d_in[15];
    const float* ad0  = (const float*)d_in[16];
    const float* b0   = (const float*)d_in[17];
    const float* w1   = (const float*)d_in[18];
    const float* as1  = (const float*)d_in[19];
    const float* ad1  = (const float*)d_in[20];
    const float* b1   = (const float*)d_in[21];
    float* out = (float*)d_out;

    float* traj_hs;
    float* graph_hs;
    if (out_size >= ENC_ELEMS + 2*SEQ_ELEMS) {
        graph_hs = out + ENC_ELEMS;
        traj_hs  = out + ENC_ELEMS + SEQ_ELEMS;
    } else {
        void* pt = nullptr; void* pg = nullptr;
        cudaGetSymbolAddress(&pt, g_traj_fb);
        cudaGetSymbolAddress(&pg, g_graph_fb);
        traj_hs  = (float*)pt;
        graph_hs = (float*)pg;
    }

    lstm_traj_kernel<<<NN/32, 256>>>(obs, h0t, c0t, WihT, WhhT, bihT, bhhT, traj_hs);
    gat0_kernel<<<SS*TT, 256>>>(traj_hs, w0, as0, ad0, b0);
    gat1_kernel<<<SS*TT, 256>>>(w1, as1, ad1, b1);
    lstm_graph_kernel<<<NN/32, 256>>>(h0g, c0g, WihG, WhhG, bihG, bhhG, graph_hs);
    concat_kernel<<<(NN*18 + 255)/256, 256>>>(z, traj_hs, graph_hs, out);
}